// round 12
// baseline (speedup 1.0000x reference)
#include <cuda_runtime.h>
#include <cuda_bf16.h>
#include <math.h>
#include <stdint.h>

#define BB   8
#define TT   2048
#define CC   512
#define LL   2048
#define CR   32
#define HH   512
#define ROWS (BB*TT)   /* 16384 */

// ---------------- scratch (static device globals; no allocation) -------------
__device__ float g_yt[CC*BB*TT];            // conv output transposed [c][b][t]
__device__ float g_y1[BB*TT*CC];            // after SE gate + residual + LN1 (fp32)
__device__ __nv_bfloat16 g_y1h[ROWS*CC];    // y1 split hi
__device__ __nv_bfloat16 g_y1l[ROWS*CC];    // y1 split lo
__device__ __nv_bfloat16 g_hh [ROWS*HH];    // GLU hidden split hi
__device__ __nv_bfloat16 g_hl [ROWS*HH];    // GLU hidden split lo
__device__ float g_z [ROWS*CC];             // down-proj output
__device__ float g_sp[BB*CC];               // time-sums for SE pooling
__device__ float g_gate[BB*CC];             // SE gate
__device__ __nv_bfloat16 g_ubh[1024*CC];    // up_w^T  [N=1024][K=512] hi
__device__ __nv_bfloat16 g_ubl[1024*CC];    // up_w^T  lo
__device__ __nv_bfloat16 g_dbh[ CC*HH];     // down_w^T [N=512][K=512] hi
__device__ __nv_bfloat16 g_dbl[ CC*HH];     // down_w^T lo
__device__ __nv_bfloat16 g_xth[CC*BB*TT];   // x^T [c][b][t] hi
__device__ __nv_bfloat16 g_xtl[CC*BB*TT];   // x^T lo

// ===================== sm_100-base PTX helpers (NO tcgen05) ==================
__device__ __forceinline__ uint32_t s2u(const void* p) {
    uint32_t a;
    asm("{ .reg .u64 t; cvta.to.shared.u64 t, %1; cvt.u32.u64 %0, t; }"
        : "=r"(a) : "l"(p));
    return a;
}
__device__ __forceinline__ void cp16(uint32_t saddr, const void* gaddr) {
    asm volatile("cp.async.cg.shared.global [%0], [%1], 16;"
                 :: "r"(saddr), "l"(gaddr));
}
#define CP_COMMIT() asm volatile("cp.async.commit_group;" ::: "memory")
#define CP_WAIT1()  asm volatile("cp.async.wait_group 1;" ::: "memory")
#define CP_WAIT0()  asm volatile("cp.async.wait_group 0;" ::: "memory")

__device__ __forceinline__ void ldmx4(uint32_t* f, uint32_t addr) {
    asm volatile("ldmatrix.sync.aligned.m8n8.x4.shared.b16 {%0,%1,%2,%3}, [%4];"
                 : "=r"(f[0]), "=r"(f[1]), "=r"(f[2]), "=r"(f[3]) : "r"(addr));
}
__device__ __forceinline__ void lds64(uint32_t& h, uint32_t& l, uint32_t a) {
    asm volatile("ld.shared.v2.u32 {%0,%1}, [%2];" : "=r"(h), "=r"(l) : "r"(a));
}
__device__ __forceinline__ void mma16816(float* d, const uint32_t* a,
                                         uint32_t b0, uint32_t b1) {
    asm volatile("mma.sync.aligned.m16n8k16.row.col.f32.bf16.bf16.f32 "
                 "{%0,%1,%2,%3}, {%4,%5,%6,%7}, {%8,%9}, {%0,%1,%2,%3};"
                 : "+f"(d[0]), "+f"(d[1]), "+f"(d[2]), "+f"(d[3])
                 : "r"(a[0]), "r"(a[1]), "r"(a[2]), "r"(a[3]), "r"(b0), "r"(b1));
}

// ============================================================================
// K0a: tiled transpose + bf16 hi/lo split of GEMM weights: W[K][N] -> [N][K].
// ============================================================================
__global__ void transpose_split_kernel(const float* __restrict__ W, int K, int N,
                                       __nv_bfloat16* __restrict__ oh,
                                       __nv_bfloat16* __restrict__ ol)
{
    __shared__ float t[32][33];
    const int n0 = blockIdx.x << 5, k0 = blockIdx.y << 5;
    const int tx = threadIdx.x, ty = threadIdx.y;
#pragma unroll
    for (int r = 0; r < 4; ++r)
        t[ty + r * 8][tx] = W[(k0 + ty + r * 8) * N + n0 + tx];
    __syncthreads();
#pragma unroll
    for (int r = 0; r < 4; ++r) {
        int n = n0 + ty + r * 8, kk = k0 + tx;
        float w = t[tx][ty + r * 8];
        __nv_bfloat16 h = __float2bfloat16(w);
        oh[n * K + kk] = h;
        ol[n * K + kk] = __float2bfloat16(w - __bfloat162float(h));
    }
}

// ============================================================================
// K0b: x[b][t][c] fp32 -> x^T[c][b][t] bf16 hi/lo. grid (C/32, T/32, B).
// ============================================================================
__global__ void prep_x_kernel(const float* __restrict__ x)
{
    __shared__ float t[32][33];
    const int c0 = blockIdx.x << 5, t0 = blockIdx.y << 5, b = blockIdx.z;
    const int tx = threadIdx.x, ty = threadIdx.y;
#pragma unroll
    for (int r = 0; r < 4; ++r)
        t[ty + r * 8][tx] = x[((size_t)(b * TT) + t0 + ty + r * 8) * CC + c0 + tx];
    __syncthreads();
#pragma unroll
    for (int r = 0; r < 4; ++r) {
        int c = c0 + ty + r * 8, tt = t0 + tx;
        float v = t[tx][ty + r * 8];
        __nv_bfloat16 h = __float2bfloat16(v);
        size_t o = ((size_t)c * BB + b) * TT + tt;
        g_xth[o] = h;
        g_xtl[o] = __float2bfloat16(v - __bfloat162float(h));
    }
}

// ============================================================================
// K1: causal depthwise conv on HMMA. CTA = one channel, 16 warps (512 thr).
// A-fragments synthesized from a PACKED (hi,lo)-interleaved krev2 table:
// 3x LDS.64 per delta (was 6x LDS.32). Warp owns 8 tiles in TWO GROUPS OF 4
// {i0, i0+32, i0+64, i0+96} (i0 = w, w+16): one A-fragment feeds up to 12 MMAs
// (4 independent acc chains), quartering A-table traffic per MMA.
// SMEM: x hi (8x4112) | x lo (8x4112) | packed krev2 (2064 x uint2 = 16512B).
// ============================================================================
#define XR 4112
#define CONV_SMEM (65792 + 16512)
__global__ __launch_bounds__(512) void conv_mma_kernel(const float* __restrict__ kg)
{
    extern __shared__ __align__(16) uint8_t smp[];
    const int tid = threadIdx.x, lane = tid & 31, w = tid >> 5;
    const int c = blockIdx.x;
    const uint32_t sbase = s2u(smp);
    const uint32_t xs_hi = sbase, xs_lo = sbase + 32896;
    const uint32_t kr2  = sbase + 65792;      // packed table
    float* sps = (float*)(smp + 65792);       // 8 floats, reused post-mainloop

    // stage x^T hi/lo: 2048 float4 over 512 threads = 4 iterations
    {
        const float4* srcH = (const float4*)(g_xth + (size_t)c * 16384);
        const float4* srcL = (const float4*)(g_xtl + (size_t)c * 16384);
#pragma unroll
        for (int r = 0; r < 4; ++r) {
            int idx = r * 512 + tid;
            int b = idx >> 8, q = idx & 255;
            float4 vh = srcH[b * 256 + q];
            float4 vl = srcL[b * 256 + q];
            *(float4*)(smp + b * XR + q * 16) = vh;
            *(float4*)(smp + 32896 + b * XR + q * 16) = vl;
        }
    }
    // build packed krev2 table: tp[idx] = {hi_pair, lo_pair}, idx = q+16
    {
        const float* kc = kg + (size_t)c * LL;
        uint2* tp = (uint2*)(smp + 65792);
        for (int idx = tid; idx < 2064; idx += 512) {
            int p0 = idx - 16, p1 = idx - 17;
            float v0 = ((unsigned)p0 < 2048u) ? kc[2047 - p0] : 0.f;
            float v1 = ((unsigned)p1 < 2048u) ? kc[2047 - p1] : 0.f;
            __nv_bfloat16 h0 = __float2bfloat16(v0), h1 = __float2bfloat16(v1);
            __nv_bfloat16 l0 = __float2bfloat16(v0 - __bfloat162float(h0));
            __nv_bfloat16 l1 = __float2bfloat16(v1 - __bfloat162float(h1));
            uint32_t hp = (uint32_t)*(unsigned short*)&h0
                        | ((uint32_t)*(unsigned short*)&h1 << 16);
            uint32_t lp = (uint32_t)*(unsigned short*)&l0
                        | ((uint32_t)*(unsigned short*)&l1 << 16);
            tp[idx] = make_uint2(hp, lp);
        }
    }
    __syncthreads();

    const int g  = lane >> 2, t4 = lane & 3;
    const uint32_t aoff = (uint32_t)((g - 2 * t4 + 16) << 3);   // uint2 elements
    const uint32_t xb = ((lane < 16) ? xs_hi : xs_lo)
                      + (uint32_t)(lane & 7) * XR + ((lane >> 3) & 1) * 16;

    float acc[8][4];
#pragma unroll
    for (int s = 0; s < 8; ++s)
#pragma unroll
        for (int q = 0; q < 4; ++q) acc[s][q] = 0.f;

#pragma unroll
    for (int grp = 0; grp < 2; ++grp) {
        const int i0 = w + (grp << 4);           // group base tile (0..31)
        const int g4 = grp << 2;                 // acc base index
        uint32_t a_ad = kr2 + aoff;
        uint32_t bad[4];
#pragma unroll
        for (int j = 0; j < 4; ++j)
            bad[j] = xb + (uint32_t)(i0 + (j << 5)) * 32;

        int d = 0;
#pragma unroll
        for (int seg = 0; seg < 4; ++seg) {      // tiles j>=seg live
            const int dend = i0 + (seg << 5);
            for (; d <= dend; ++d) {
                uint32_t ah[4], al[4];
                lds64(ah[0], al[0], a_ad);
                lds64(ah[1], al[1], a_ad + 64);
                lds64(ah[2], al[2], a_ad - 64);
                ah[3] = ah[0]; al[3] = al[0];
                uint32_t bf[4][4];
#pragma unroll
                for (int j = 0; j < 4; ++j)
                    if (j >= seg) ldmx4(bf[j], bad[j]);
#pragma unroll
                for (int j = 0; j < 4; ++j)
                    if (j >= seg) mma16816(acc[g4 + j], ah, bf[j][0], bf[j][1]);
#pragma unroll
                for (int j = 0; j < 4; ++j)
                    if (j >= seg) mma16816(acc[g4 + j], ah, bf[j][2], bf[j][3]);
#pragma unroll
                for (int j = 0; j < 4; ++j)
                    if (j >= seg) mma16816(acc[g4 + j], al, bf[j][0], bf[j][1]);
                a_ad += 128;
#pragma unroll
                for (int j = 0; j < 4; ++j) bad[j] -= 32;
            }
        }
    }
    __syncthreads();

    // epilogue: accs -> SMEM (reuse x region as fp32 [8][2056]); zero sps
    float* ys = (float*)smp;
    if (tid < 8) sps[tid] = 0.f;
    const int rr = lane >> 2, cb = (lane & 3) << 1;
#pragma unroll
    for (int s = 0; s < 8; ++s) {
        const int i = w + ((s >> 2) << 4) + ((s & 3) << 5);  // tile index
        const int t0 = i << 4;
        ys[cb * 2056 + t0 + rr]           = acc[s][0];
        ys[(cb + 1) * 2056 + t0 + rr]     = acc[s][1];
        ys[cb * 2056 + t0 + rr + 8]       = acc[s][2];
        ys[(cb + 1) * 2056 + t0 + rr + 8] = acc[s][3];
    }
    __syncthreads();

    // warp w: batch row w>>1, half w&1: coalesced y^T store + SE partial sum
    {
        const int b = w >> 1, hf = w & 1;
        float4* dst = (float4*)(g_yt + ((size_t)c * BB + b) * TT);
        float ssum = 0.f;
#pragma unroll
        for (int q = 0; q < 8; ++q) {
            int f4 = hf * 256 + q * 32 + lane;
            float4 v = *(float4*)&ys[b * 2056 + f4 * 4];
            dst[f4] = v;
            ssum += v.x + v.y + v.z + v.w;
        }
#pragma unroll
        for (int o = 16; o; o >>= 1) ssum += __shfl_xor_sync(0xffffffffu, ssum, o);
        if (lane == 0) atomicAdd(&sps[b], ssum);
    }
    __syncthreads();
    if (tid < 8) g_sp[tid * CC + c] = sps[tid];
}

// ============================================================================
// K3: SE bottleneck MLP + sigmoid.
// ============================================================================
__global__ __launch_bounds__(256) void se_kernel(const float* __restrict__ w1,
                                                 const float* __restrict__ b1,
                                                 const float* __restrict__ w2,
                                                 const float* __restrict__ b2)
{
    __shared__ float s_sh[CC];
    __shared__ float h_sh[CR];
    const int b = blockIdx.x, tid = threadIdx.x;
#pragma unroll
    for (int cb = 0; cb < 2; ++cb) {
        int c = tid + (cb << 8);
        s_sh[c] = g_sp[b * CC + c] * (1.0f / TT);
    }
    __syncthreads();
    if (tid < CR) {
        float a = b1[tid];
        for (int c = 0; c < CC; ++c) a += s_sh[c] * w1[c * CR + tid];
        h_sh[tid] = fmaxf(a, 0.f);
    }
    __syncthreads();
#pragma unroll
    for (int cb = 0; cb < 2; ++cb) {
        int c = tid + (cb << 8);
        float a = b2[c];
#pragma unroll
        for (int j = 0; j < CR; ++j) a += h_sh[j] * w2[j * CC + c];
        g_gate[b * CC + c] = 1.f / (1.f + expf(-a));
    }
}

// ============================================================================
// K4: fused y^T transpose + gate + residual + LN1. grid (T/32, B), 256 thr.
// ============================================================================
#define LN1T_SMEM (32 * 520 * 4)
__global__ __launch_bounds__(256) void ln1t_kernel(const float* __restrict__ x,
                                                   const float* __restrict__ w,
                                                   const float* __restrict__ bia)
{
    extern __shared__ float ys[];    // [32][520]
    const int t0 = (int)blockIdx.x << 5, b = blockIdx.y;
    const int tid = threadIdx.x, lane = tid & 31, wp = tid >> 5;

#pragma unroll
    for (int i = 0; i < 16; ++i) {
        int idx = i * 256 + tid;
        int c = idx >> 3, q = idx & 7;
        float4 v = *(const float4*)&g_yt[((size_t)c * BB + b) * TT + t0 + (q << 2)];
        ys[((q << 2) + 0) * 520 + c] = v.x;
        ys[((q << 2) + 1) * 520 + c] = v.y;
        ys[((q << 2) + 2) * 520 + c] = v.z;
        ys[((q << 2) + 3) * 520 + c] = v.w;
    }
    __syncthreads();

    const float4* gr = (const float4*)(g_gate + b * CC);
    const float4* w4p = (const float4*)w;
    const float4* b4p = (const float4*)bia;

#pragma unroll
    for (int rsub = 0; rsub < 4; ++rsub) {
        const int tt  = (wp << 2) + rsub;
        const int row = b * TT + t0 + tt;
        const float4* xr = (const float4*)(x + (size_t)row * CC);

        float4 v[4];
        float s = 0.f, sq = 0.f;
#pragma unroll
        for (int i = 0; i < 4; ++i) {
            int c4 = lane + (i << 5);
            float4 yv = *(float4*)&ys[tt * 520 + (c4 << 2)];
            float4 xv = xr[c4], gv = gr[c4], t;
            t.x = xv.x + yv.x * gv.x; t.y = xv.y + yv.y * gv.y;
            t.z = xv.z + yv.z * gv.z; t.w = xv.w + yv.w * gv.w;
            v[i] = t;
            s  += t.x + t.y + t.z + t.w;
            sq += t.x*t.x + t.y*t.y + t.z*t.z + t.w*t.w;
        }
#pragma unroll
        for (int o = 16; o; o >>= 1) {
            s  += __shfl_xor_sync(0xffffffffu, s,  o);
            sq += __shfl_xor_sync(0xffffffffu, sq, o);
        }
        float m    = s * (1.f / CC);
        float rstd = rsqrtf(sq * (1.f / CC) - m * m + 1e-5f);
        float4* out = (float4*)(g_y1 + (size_t)row * CC);
        __nv_bfloat162* oh = (__nv_bfloat162*)(g_y1h + (size_t)row * CC);
        __nv_bfloat162* ol = (__nv_bfloat162*)(g_y1l + (size_t)row * CC);
#pragma unroll
        for (int i = 0; i < 4; ++i) {
            int c4 = lane + (i << 5);
            float4 wv = w4p[c4], bv = b4p[c4], t = v[i], o4;
            o4.x = (t.x - m) * rstd * wv.x + bv.x;
            o4.y = (t.y - m) * rstd * wv.y + bv.y;
            o4.z = (t.z - m) * rstd * wv.z + bv.z;
            o4.w = (t.w - m) * rstd * wv.w + bv.w;
            out[c4] = o4;
            __nv_bfloat16 hx = __float2bfloat16(o4.x), hy = __float2bfloat16(o4.y);
            __nv_bfloat16 hz = __float2bfloat16(o4.z), hw = __float2bfloat16(o4.w);
            oh[c4*2+0] = __nv_bfloat162(hx, hy);
            oh[c4*2+1] = __nv_bfloat162(hz, hw);
            ol[c4*2+0] = __nv_bfloat162(__float2bfloat16(o4.x - __bfloat162float(hx)),
                                        __float2bfloat16(o4.y - __bfloat162float(hy)));
            ol[c4*2+1] = __nv_bfloat162(__float2bfloat16(o4.z - __bfloat162float(hz)),
                                        __float2bfloat16(o4.w - __bfloat162float(hw)));
        }
    }
}

// ============================================================================
// K5: fused up-GEMM + GLU on HMMA. CTA covers 64 a-cols + the SAME 64 g-cols.
// ============================================================================
__global__ __launch_bounds__(256) void up_gemm_glu_kernel(
    const __nv_bfloat16* __restrict__ Ahi, const __nv_bfloat16* __restrict__ Alo,
    const __nv_bfloat16* __restrict__ Bhi, const __nv_bfloat16* __restrict__ Blo,
    const float* __restrict__ ub)
{
    __shared__ __align__(128) uint8_t smem[2 * 20480];
    const uint32_t sbase = s2u(smem);

    const int tid  = threadIdx.x;
    const int lane = tid & 31;
    const int wid  = tid >> 5;
    const int wm   = wid & 3;
    const int wn   = wid >> 2;
    const int m0   = (int)blockIdx.y << 7;
    const int n0   = (int)blockIdx.x << 6;   // 64 a-cols per CTA

    const int lr = (lane & 7) + ((lane >> 3) & 1) * 8;
    const int lc = (lane >> 4) & 1;

    float acc[2][8][4];   // no 0..3 = a-cols, 4..7 = g-cols
#pragma unroll
    for (int a = 0; a < 2; ++a)
#pragma unroll
        for (int b = 0; b < 8; ++b)
#pragma unroll
            for (int c = 0; c < 4; ++c) acc[a][b][c] = 0.f;

    auto load_chunk = [&](int it, int buf) {
        const int s = it >> 4, kc = it & 15;
        const __nv_bfloat16* Ag = (s < 2) ? Ahi : Alo;
        const __nv_bfloat16* Bg = (s == 1) ? Blo : Bhi;
        const int k0 = kc << 5;
#pragma unroll
        for (int half = 0; half < 2; ++half) {
            int e   = tid + (half << 8);
            int row = e >> 2, c = e & 3;
            uint32_t sA = sbase + buf * 20480 + row * 80 + c * 16;
            cp16(sA, Ag + (size_t)(m0 + row) * CC + k0 + c * 8);
            int ng  = (row < 64) ? (n0 + row) : (448 + n0 + row);  // g rows at +512
            uint32_t sB = sbase + buf * 20480 + 10240 + row * 80 + c * 16;
            cp16(sB, Bg + (size_t)ng * CC + k0 + c * 8);
        }
        CP_COMMIT();
    };

    load_chunk(0, 0);

    for (int it = 0; it < 48; ++it) {
        const int buf = it & 1;
        if (it < 47) load_chunk(it + 1, buf ^ 1);
        if (it < 47) CP_WAIT1(); else CP_WAIT0();
        __syncthreads();

        const uint32_t abase = sbase + buf * 20480;
        const uint32_t bbase = abase + 10240;
#pragma unroll
        for (int kk = 0; kk < 2; ++kk) {
            uint32_t af[2][4], bf_[4][4];
#pragma unroll
            for (int mt = 0; mt < 2; ++mt)
                ldmx4(af[mt], abase + (uint32_t)((wm * 32 + mt * 16 + lr) * 80 + kk * 32 + lc * 16));
#pragma unroll
            for (int pr = 0; pr < 4; ++pr) {
                int rbase = (pr < 2) ? (wn * 32 + pr * 16) : (64 + wn * 32 + (pr - 2) * 16);
                ldmx4(bf_[pr], bbase + (uint32_t)((rbase + lr) * 80 + kk * 32 + lc * 16));
            }
#pragma unroll
            for (int mt = 0; mt < 2; ++mt)
#pragma unroll
                for (int no = 0; no < 8; ++no) {
                    uint32_t b0 = bf_[no >> 1][(no & 1)];
                    uint32_t b1 = bf_[no >> 1][(no & 1) + 2];
                    mma16816(acc[mt][no], af[mt], b0, b1);
                }
        }
        __syncthreads();
    }

    const int rr = lane >> 2, cc2 = (lane & 3) << 1;
#pragma unroll
    for (int mt = 0; mt < 2; ++mt) {
#pragma unroll
        for (int no = 0; no < 4; ++no) {
            int m = m0 + wm * 32 + mt * 16 + rr;
            int n = n0 + wn * 32 + no * 8 + cc2;
            float ba0 = ub[n], ba1 = ub[n + 1];
            float bg0 = ub[512 + n], bg1 = ub[512 + n + 1];
#pragma unroll
            for (int half = 0; half < 2; ++half) {
                int mm = m + half * 8;
                float a0 = acc[mt][no][half * 2 + 0] + ba0;
                float a1 = acc[mt][no][half * 2 + 1] + ba1;
                float g0 = acc[mt][no + 4][half * 2 + 0] + bg0;
                float g1 = acc[mt][no + 4][half * 2 + 1] + bg1;
                float h0 = 0.5f * a0 * (1.0f + erff(a0 * 0.70710678118654752f))
                         * (1.f / (1.f + expf(-g0)));
                float h1 = 0.5f * a1 * (1.0f + erff(a1 * 0.70710678118654752f))
                         * (1.f / (1.f + expf(-g1)));
                __nv_bfloat16 hh0 = __float2bfloat16(h0);
                __nv_bfloat16 hh1 = __float2bfloat16(h1);
                *(__nv_bfloat162*)&g_hh[(size_t)mm * HH + n] = __nv_bfloat162(hh0, hh1);
                *(__nv_bfloat162*)&g_hl[(size_t)mm * HH + n] = __nv_bfloat162(
                    __float2bfloat16(h0 - __bfloat162float(hh0)),
                    __float2bfloat16(h1 - __bfloat162float(hh1)));
            }
        }
    }
}

// ============================================================================
// K6: split-bf16 3-term GEMM on HMMA (down-projection).
// ============================================================================
__global__ __launch_bounds__(256) void down_gemm_kernel(
    const __nv_bfloat16* __restrict__ Ahi, const __nv_bfloat16* __restrict__ Alo,
    const __nv_bfloat16* __restrict__ Bhi, const __nv_bfloat16* __restrict__ Blo,
    float* __restrict__ out, const float* __restrict__ bias)
{
    __shared__ __align__(128) uint8_t smem[2 * 20480];
    const uint32_t sbase = s2u(smem);

    const int tid  = threadIdx.x;
    const int lane = tid & 31;
    const int wid  = tid >> 5;
    const int wm   = wid & 3;
    const int wn   = wid >> 2;
    const int m0   = (int)blockIdx.y << 7;
    const int n0   = (int)blockIdx.x << 7;

    const int lr = (lane & 7) + ((lane >> 3) & 1) * 8;
    const int lc = (lane >> 4) & 1;

    float acc[2][8][4];
#pragma unroll
    for (int a = 0; a < 2; ++a)
#pragma unroll
        for (int b = 0; b < 8; ++b)
#pragma unroll
            for (int c = 0; c < 4; ++c) acc[a][b][c] = 0.f;

    auto load_chunk = [&](int it, int buf) {
        const int s = it >> 4, kc = it & 15;
        const __nv_bfloat16* Ag = (s < 2) ? Ahi : Alo;
        const __nv_bfloat16* Bg = (s == 1) ? Blo : Bhi;
        const int k0 = kc << 5;
#pragma unroll
        for (int half = 0; half < 2; ++half) {
            int e   = tid + (half << 8);
            int row = e >> 2, c = e & 3;
            uint32_t sA = sbase + buf * 20480 + row * 80 + c * 16;
            cp16(sA, Ag + (size_t)(m0 + row) * CC + k0 + c * 8);
            uint32_t sB = sbase + buf * 20480 + 10240 + row * 80 + c * 16;
            cp16(sB, Bg + (size_t)(n0 + row) * CC + k0 + c * 8);
        }
        CP_COMMIT();
    };

    load_chunk(0, 0);

    for (int it = 0; it < 48; ++it) {
        const int buf = it & 1;
        if (it < 47) load_chunk(it + 1, buf ^ 1);
        if (it < 47) CP_WAIT1(); else CP_WAIT0();
        __syncthreads();

        const uint32_t abase = sbase + buf * 20480;
        const uint32_t bbase = abase + 10240;
#pragma unroll
        for (int kk = 0; kk < 2; ++kk) {
            uint32_t af[2][4], bf_[4][4];
#pragma unroll
            for (int mt = 0; mt < 2; ++mt)
                ldmx4(af[mt], abase + (uint32_t)((wm * 32 + mt * 16 + lr) * 80 + kk * 32 + lc * 16));
#pragma unroll
            for (int pr = 0; pr < 4; ++pr)
                ldmx4(bf_[pr], bbase + (uint32_t)((wn * 64 + pr * 16 + lr) * 80 + kk * 32 + lc * 16));
#pragma unroll
            for (int mt = 0; mt < 2; ++mt)
#pragma unroll
                for (int no = 0; no < 8; ++no) {
                    uint32_t b0 = bf_[no >> 1][(no & 1)];
                    uint32_t b1 = bf_[no >> 1][(no & 1) + 2];
                    mma16816(acc[mt][no], af[mt], b0, b1);
                }
        }
        __syncthreads();
    }

    const int rr = lane >> 2, cc2 = (lane & 3) << 1;
#pragma unroll
    for (int mt = 0; mt < 2; ++mt) {
#pragma unroll
        for (int no = 0; no < 8; ++no) {
            int m = m0 + wm * 32 + mt * 16 + rr;
            int n = n0 + wn * 64 + no * 8 + cc2;
            float b0 = bias[n], b1 = bias[n + 1];
            out[(size_t)m * CC + n]           = acc[mt][no][0] + b0;
            out[(size_t)m * CC + n + 1]       = acc[mt][no][1] + b1;
            out[(size_t)(m + 8) * CC + n]     = acc[mt][no][2] + b0;
            out[(size_t)(m + 8) * CC + n + 1] = acc[mt][no][3] + b1;
        }
    }
}

// ============================================================================
// K7: z2 = LN(y1+z, mix); out = LN(y1+z2, ln2). warp per row, fused.
// ============================================================================
__global__ __launch_bounds__(256) void ln_final_kernel(const float* __restrict__ mw,
                                                       const float* __restrict__ mb,
                                                       const float* __restrict__ w2,
                                                       const float* __restrict__ b2,
                                                       float* __restrict__ out)
{
    const int row  = blockIdx.x * 8 + (threadIdx.x >> 5);
    const int lane = threadIdx.x & 31;
    const float4* y1r = (const float4*)(g_y1 + (size_t)row * CC);
    const float4* zr  = (const float4*)(g_z  + (size_t)row * CC);

    float4 y1v[4], t[4];
    float s = 0.f, sq = 0.f;
#pragma unroll
    for (int i = 0; i < 4; ++i) {
        int c4 = lane + (i << 5);
        float4 yv = y1r[c4], zv = zr[c4], u;
        y1v[i] = yv;
        u.x = yv.x + zv.x; u.y = yv.y + zv.y; u.z = yv.z + zv.z; u.w = yv.w + zv.w;
        t[i] = u;
        s  += u.x + u.y + u.z + u.w;
        sq += u.x*u.x + u.y*u.y + u.z*u.z + u.w*u.w;
    }
#pragma unroll
    for (int o = 16; o; o >>= 1) {
        s  += __shfl_xor_sync(0xffffffffu, s,  o);
        sq += __shfl_xor_sync(0xffffffffu, sq, o);
    }
    float m    = s * (1.f / CC);
    float rstd = rsqrtf(sq * (1.f / CC) - m * m + 1e-5f);

    const float4* mw4 = (const float4*)mw;
    const float4* mb4 = (const float4*)mb;
    float s2 = 0.f, sq2 = 0.f;
#pragma unroll
    for (int i = 0; i < 4; ++i) {
        int c4 = lane + (i << 5);
        float4 wv = mw4[c4], bv = mb4[c4], u = t[i], yv = y1v[i], u2;
        u2.x = yv.x + ((u.x - m) * rstd * wv.x + bv.x);
        u2.y = yv.y + ((u.y - m) * rstd * wv.y + bv.y);
        u2.z = yv.z + ((u.z - m) * rstd * wv.z + bv.z);
        u2.w = yv.w + ((u.w - m) * rstd * wv.w + bv.w);
        t[i] = u2;
        s2  += u2.x + u2.y + u2.z + u2.w;
        sq2 += u2.x*u2.x + u2.y*u2.y + u2.z*u2.z + u2.w*u2.w;
    }
#pragma unroll
    for (int o = 16; o; o >>= 1) {
        s2  += __shfl_xor_sync(0xffffffffu, s2,  o);
        sq2 += __shfl_xor_sync(0xffffffffu, sq2, o);
    }
    float m2    = s2 * (1.f / CC);
    float rstd2 = rsqrtf(sq2 * (1.f / CC) - m2 * m2 + 1e-5f);

    float4* orow = (float4*)(out + (size_t)row * CC);
    const float4* w24 = (const float4*)w2;
    const float4* b24 = (const float4*)b2;
#pragma unroll
    for (int i = 0; i < 4; ++i) {
        int c4 = lane + (i << 5);
        float4 wv = w24[c4], bv = b24[c4], u = t[i], o4;
        o4.x = (u.x - m2) * rstd2 * wv.x + bv.x;
        o4.y = (u.y - m2) * rstd2 * wv.y + bv.y;
        o4.z = (u.z - m2) * rstd2 * wv.z + bv.z;
        o4.w = (u.w - m2) * rstd2 * wv.w + bv.w;
        orow[c4] = o4;
    }
}

// ============================================================================
extern "C" void kernel_launch(void* const* d_in, const int* in_sizes, int n_in,
                              void* d_out, int out_size)
{
    const float* x        = (const float*)d_in[0];
    const float* k        = (const float*)d_in[1];
    const float* se_w1    = (const float*)d_in[2];
    const float* se_b1    = (const float*)d_in[3];
    const float* se_w2    = (const float*)d_in[4];
    const float* se_b2    = (const float*)d_in[5];
    const float* ln1_w    = (const float*)d_in[6];
    const float* ln1_b    = (const float*)d_in[7];
    const float* up_w     = (const float*)d_in[8];
    const float* up_b     = (const float*)d_in[9];
    const float* down_w   = (const float*)d_in[10];
    const float* down_b   = (const float*)d_in[11];
    const float* mix_ln_w = (const float*)d_in[12];
    const float* mix_ln_b = (const float*)d_in[13];
    const float* ln2_w    = (const float*)d_in[14];
    const float* ln2_b    = (const float*)d_in[15];
    float* out = (float*)d_out;

    __nv_bfloat16 *ubh, *ubl, *dbh, *dbl, *y1h, *y1l, *hh, *hl;
    float *zz;
    cudaGetSymbolAddress((void**)&ubh, g_ubh);
    cudaGetSymbolAddress((void**)&ubl, g_ubl);
    cudaGetSymbolAddress((void**)&dbh, g_dbh);
    cudaGetSymbolAddress((void**)&dbl, g_dbl);
    cudaGetSymbolAddress((void**)&y1h, g_y1h);
    cudaGetSymbolAddress((void**)&y1l, g_y1l);
    cudaGetSymbolAddress((void**)&hh,  g_hh);
    cudaGetSymbolAddress((void**)&hl,  g_hl);
    cudaGetSymbolAddress((void**)&zz,  g_z);

    cudaFuncSetAttribute(conv_mma_kernel,
                         cudaFuncAttributeMaxDynamicSharedMemorySize, CONV_SMEM);
    cudaFuncSetAttribute(ln1t_kernel,
                         cudaFuncAttributeMaxDynamicSharedMemorySize, LN1T_SMEM);

    transpose_split_kernel<<<dim3(1024/32, 512/32), dim3(32, 8)>>>(up_w, CC, 1024, ubh, ubl);
    transpose_split_kernel<<<dim3( 512/32, 512/32), dim3(32, 8)>>>(down_w, HH, 512, dbh, dbl);
    prep_x_kernel   <<<dim3(CC/32, TT/32, BB), dim3(32, 8)>>>(x);
    conv_mma_kernel <<<CC, 512, CONV_SMEM>>>(k);
    se_kernel       <<<BB, 256>>>(se_w1, se_b1, se_w2, se_b2);
    ln1t_kernel     <<<dim3(TT/32, BB), 256, LN1T_SMEM>>>(x, ln1_w, ln1_b);
    up_gemm_glu_kernel<<<dim3(8, ROWS / 128), 256>>>(y1h, y1l, ubh, ubl, up_b);
    down_gemm_kernel  <<<dim3(4, ROWS / 128), 256>>>(hh, hl, dbh, dbl, zz, down_b);
    ln_final_kernel <<<ROWS / 8, 256>>>(mix_ln_w, mix_ln_b, ln2_w, ln2_b, out);
}

// round 13
// speedup vs baseline: 1.0924x; 1.0924x over previous
#include <cuda_runtime.h>
#include <cuda_bf16.h>
#include <math.h>
#include <stdint.h>

#define BB   8
#define TT   2048
#define CC   512
#define LL   2048
#define CR   32
#define HH   512
#define ROWS (BB*TT)   /* 16384 */

// ---------------- scratch (static device globals; no allocation) -------------
__device__ float g_yt[CC*BB*TT];            // conv output transposed [c][b][t]
__device__ float g_y1[BB*TT*CC];            // after SE gate + residual + LN1 (fp32)
__device__ __nv_bfloat16 g_y1h[ROWS*CC];    // y1 split hi
__device__ __nv_bfloat16 g_y1l[ROWS*CC];    // y1 split lo
__device__ __nv_bfloat16 g_hh [ROWS*HH];    // GLU hidden split hi
__device__ __nv_bfloat16 g_hl [ROWS*HH];    // GLU hidden split lo
__device__ float g_z [ROWS*CC];             // down-proj output
__device__ float g_sp[BB*CC];               // time-sums for SE pooling
__device__ float g_gate[BB*CC];             // SE gate
__device__ __nv_bfloat16 g_ubh[1024*CC];    // up_w^T  [N=1024][K=512] hi
__device__ __nv_bfloat16 g_ubl[1024*CC];    // up_w^T  lo
__device__ __nv_bfloat16 g_dbh[ CC*HH];     // down_w^T [N=512][K=512] hi
__device__ __nv_bfloat16 g_dbl[ CC*HH];     // down_w^T lo
__device__ __nv_bfloat16 g_xth[CC*BB*TT];   // x^T [c][b][t] hi
__device__ __nv_bfloat16 g_xtl[CC*BB*TT];   // x^T lo

// ===================== sm_100-base PTX helpers (NO tcgen05) ==================
__device__ __forceinline__ uint32_t s2u(const void* p) {
    uint32_t a;
    asm("{ .reg .u64 t; cvta.to.shared.u64 t, %1; cvt.u32.u64 %0, t; }"
        : "=r"(a) : "l"(p));
    return a;
}
__device__ __forceinline__ void cp16(uint32_t saddr, const void* gaddr) {
    asm volatile("cp.async.cg.shared.global [%0], [%1], 16;"
                 :: "r"(saddr), "l"(gaddr));
}
#define CP_COMMIT() asm volatile("cp.async.commit_group;" ::: "memory")
#define CP_WAIT1()  asm volatile("cp.async.wait_group 1;" ::: "memory")
#define CP_WAIT0()  asm volatile("cp.async.wait_group 0;" ::: "memory")

__device__ __forceinline__ void ldmx4(uint32_t* f, uint32_t addr) {
    asm volatile("ldmatrix.sync.aligned.m8n8.x4.shared.b16 {%0,%1,%2,%3}, [%4];"
                 : "=r"(f[0]), "=r"(f[1]), "=r"(f[2]), "=r"(f[3]) : "r"(addr));
}
__device__ __forceinline__ void lds64(uint32_t& h, uint32_t& l, uint32_t a) {
    asm volatile("ld.shared.v2.u32 {%0,%1}, [%2];" : "=r"(h), "=r"(l) : "r"(a));
}
__device__ __forceinline__ void mma16816(float* d, const uint32_t* a,
                                         uint32_t b0, uint32_t b1) {
    asm volatile("mma.sync.aligned.m16n8k16.row.col.f32.bf16.bf16.f32 "
                 "{%0,%1,%2,%3}, {%4,%5,%6,%7}, {%8,%9}, {%0,%1,%2,%3};"
                 : "+f"(d[0]), "+f"(d[1]), "+f"(d[2]), "+f"(d[3])
                 : "r"(a[0]), "r"(a[1]), "r"(a[2]), "r"(a[3]), "r"(b0), "r"(b1));
}

// ============================================================================
// K0a: tiled transpose + bf16 hi/lo split of GEMM weights: W[K][N] -> [N][K].
// ============================================================================
__global__ void transpose_split_kernel(const float* __restrict__ W, int K, int N,
                                       __nv_bfloat16* __restrict__ oh,
                                       __nv_bfloat16* __restrict__ ol)
{
    __shared__ float t[32][33];
    const int n0 = blockIdx.x << 5, k0 = blockIdx.y << 5;
    const int tx = threadIdx.x, ty = threadIdx.y;
#pragma unroll
    for (int r = 0; r < 4; ++r)
        t[ty + r * 8][tx] = W[(k0 + ty + r * 8) * N + n0 + tx];
    __syncthreads();
#pragma unroll
    for (int r = 0; r < 4; ++r) {
        int n = n0 + ty + r * 8, kk = k0 + tx;
        float w = t[tx][ty + r * 8];
        __nv_bfloat16 h = __float2bfloat16(w);
        oh[n * K + kk] = h;
        ol[n * K + kk] = __float2bfloat16(w - __bfloat162float(h));
    }
}

// ============================================================================
// K0b: x[b][t][c] fp32 -> x^T[c][b][t] bf16 hi/lo. grid (C/32, T/32, B).
// ============================================================================
__global__ void prep_x_kernel(const float* __restrict__ x)
{
    __shared__ float t[32][33];
    const int c0 = blockIdx.x << 5, t0 = blockIdx.y << 5, b = blockIdx.z;
    const int tx = threadIdx.x, ty = threadIdx.y;
#pragma unroll
    for (int r = 0; r < 4; ++r)
        t[ty + r * 8][tx] = x[((size_t)(b * TT) + t0 + ty + r * 8) * CC + c0 + tx];
    __syncthreads();
#pragma unroll
    for (int r = 0; r < 4; ++r) {
        int c = c0 + ty + r * 8, tt = t0 + tx;
        float v = t[tx][ty + r * 8];
        __nv_bfloat16 h = __float2bfloat16(v);
        size_t o = ((size_t)c * BB + b) * TT + tt;
        g_xth[o] = h;
        g_xtl[o] = __float2bfloat16(v - __bfloat162float(h));
    }
}

// ============================================================================
// K1: causal depthwise conv on HMMA. CTA = one channel, 16 warps (512 thr).
// R9 structure (known-good: regs=64, no spills, pairing (s, s+4), 2 live
// B-chains) with ONE change: A-fragments read from a PACKED (hi,lo) uint2
// krev2 table via 3x LDS.64 per delta instead of 6x LDS.32 (same bytes,
// half the A-side smem instructions; R9 profile showed L1-pipe-bound 76.6%).
// SMEM: x hi (8x4112) | x lo (8x4112) | packed krev2 (2064 x uint2 = 16512B).
// ============================================================================
#define XR 4112
#define CONV_SMEM (65792 + 16512)
__global__ __launch_bounds__(512) void conv_mma_kernel(const float* __restrict__ kg)
{
    extern __shared__ __align__(16) uint8_t smp[];
    const int tid = threadIdx.x, lane = tid & 31, w = tid >> 5;
    const int c = blockIdx.x;
    const uint32_t sbase = s2u(smp);
    const uint32_t xs_hi = sbase, xs_lo = sbase + 32896;
    const uint32_t kr2 = sbase + 65792;       // packed table
    float* sps = (float*)(smp + 65792);       // 8 floats, reused post-mainloop

    // stage x^T hi/lo: 2048 float4 over 512 threads = 4 iterations
    {
        const float4* srcH = (const float4*)(g_xth + (size_t)c * 16384);
        const float4* srcL = (const float4*)(g_xtl + (size_t)c * 16384);
#pragma unroll
        for (int r = 0; r < 4; ++r) {
            int idx = r * 512 + tid;
            int b = idx >> 8, q = idx & 255;
            float4 vh = srcH[b * 256 + q];
            float4 vl = srcL[b * 256 + q];
            *(float4*)(smp + b * XR + q * 16) = vh;
            *(float4*)(smp + 32896 + b * XR + q * 16) = vl;
        }
    }
    // build packed krev2 table: tp[idx] = {hi_pair, lo_pair}, idx = q + 16
    {
        const float* kc = kg + (size_t)c * LL;
        uint2* tp = (uint2*)(smp + 65792);
        for (int idx = tid; idx < 2064; idx += 512) {
            int p0 = idx - 16, p1 = idx - 17;
            float v0 = ((unsigned)p0 < 2048u) ? kc[2047 - p0] : 0.f;
            float v1 = ((unsigned)p1 < 2048u) ? kc[2047 - p1] : 0.f;
            __nv_bfloat16 h0 = __float2bfloat16(v0), h1 = __float2bfloat16(v1);
            __nv_bfloat16 l0 = __float2bfloat16(v0 - __bfloat162float(h0));
            __nv_bfloat16 l1 = __float2bfloat16(v1 - __bfloat162float(h1));
            uint32_t hp = (uint32_t)*(unsigned short*)&h0
                        | ((uint32_t)*(unsigned short*)&h1 << 16);
            uint32_t lp = (uint32_t)*(unsigned short*)&l0
                        | ((uint32_t)*(unsigned short*)&l1 << 16);
            tp[idx] = make_uint2(hp, lp);
        }
    }
    __syncthreads();

    const int g  = lane >> 2, t4 = lane & 3;
    const uint32_t aoff = (uint32_t)((g - 2 * t4 + 16) << 3);   // uint2 entries
    const uint32_t xb = ((lane < 16) ? xs_hi : xs_lo)
                      + (uint32_t)(lane & 7) * XR + ((lane >> 3) & 1) * 16;

    float acc[8][4];
#pragma unroll
    for (int s = 0; s < 8; ++s)
#pragma unroll
        for (int q = 0; q < 4; ++q) acc[s][q] = 0.f;

#pragma unroll
    for (int s = 0; s < 4; ++s) {
        const int ia = w + (s << 4);         // lower tile index  (0..63)
        const int ib = ia + 64;              // upper tile index  (64..127)
        uint32_t a_ad = kr2 + aoff;
        uint32_t bad_a = xb + (uint32_t)ia * 32;
        uint32_t bad_b = xb + (uint32_t)ib * 32;

        for (int d = 0; d <= ia; ++d) {      // both tiles live
            uint32_t ah[4], al[4], ba[4], bb[4];
            lds64(ah[0], al[0], a_ad);
            lds64(ah[1], al[1], a_ad + 64);
            lds64(ah[2], al[2], a_ad - 64);
            ah[3] = ah[0]; al[3] = al[0];
            ldmx4(ba, bad_a);                // ba[0..1]=hi, ba[2..3]=lo
            ldmx4(bb, bad_b);
            mma16816(acc[s],     ah, ba[0], ba[1]);
            mma16816(acc[s + 4], ah, bb[0], bb[1]);
            mma16816(acc[s],     ah, ba[2], ba[3]);
            mma16816(acc[s + 4], ah, bb[2], bb[3]);
            mma16816(acc[s],     al, ba[0], ba[1]);
            mma16816(acc[s + 4], al, bb[0], bb[1]);
            a_ad += 128; bad_a -= 32; bad_b -= 32;
        }
        for (int d = ia + 1; d <= ib; ++d) { // only upper tile live
            uint32_t ah[4], al[4], bb[4];
            lds64(ah[0], al[0], a_ad);
            lds64(ah[1], al[1], a_ad + 64);
            lds64(ah[2], al[2], a_ad - 64);
            ah[3] = ah[0]; al[3] = al[0];
            ldmx4(bb, bad_b);
            mma16816(acc[s + 4], ah, bb[0], bb[1]);
            mma16816(acc[s + 4], ah, bb[2], bb[3]);
            mma16816(acc[s + 4], al, bb[0], bb[1]);
            a_ad += 128; bad_b -= 32;
        }
    }
    __syncthreads();

    // epilogue: accs -> SMEM (reuse x region as fp32 [8][2056]); zero sps
    float* ys = (float*)smp;
    if (tid < 8) sps[tid] = 0.f;
    const int rr = lane >> 2, cb = (lane & 3) << 1;
#pragma unroll
    for (int s = 0; s < 8; ++s) {
        const int t0 = (w + ((s & 3) << 4) + ((s >> 2) << 6)) << 4;  // tiles w+16s', +64
        ys[cb * 2056 + t0 + rr]           = acc[s][0];
        ys[(cb + 1) * 2056 + t0 + rr]     = acc[s][1];
        ys[cb * 2056 + t0 + rr + 8]       = acc[s][2];
        ys[(cb + 1) * 2056 + t0 + rr + 8] = acc[s][3];
    }
    __syncthreads();

    // warp w: batch row w>>1, half w&1: coalesced y^T store + SE partial sum
    {
        const int b = w >> 1, hf = w & 1;
        float4* dst = (float4*)(g_yt + ((size_t)c * BB + b) * TT);
        float ssum = 0.f;
#pragma unroll
        for (int q = 0; q < 8; ++q) {
            int f4 = hf * 256 + q * 32 + lane;
            float4 v = *(float4*)&ys[b * 2056 + f4 * 4];
            dst[f4] = v;
            ssum += v.x + v.y + v.z + v.w;
        }
#pragma unroll
        for (int o = 16; o; o >>= 1) ssum += __shfl_xor_sync(0xffffffffu, ssum, o);
        if (lane == 0) atomicAdd(&sps[b], ssum);
    }
    __syncthreads();
    if (tid < 8) g_sp[tid * CC + c] = sps[tid];
}

// ============================================================================
// K3: SE bottleneck MLP + sigmoid.
// ============================================================================
__global__ __launch_bounds__(256) void se_kernel(const float* __restrict__ w1,
                                                 const float* __restrict__ b1,
                                                 const float* __restrict__ w2,
                                                 const float* __restrict__ b2)
{
    __shared__ float s_sh[CC];
    __shared__ float h_sh[CR];
    const int b = blockIdx.x, tid = threadIdx.x;
#pragma unroll
    for (int cb = 0; cb < 2; ++cb) {
        int c = tid + (cb << 8);
        s_sh[c] = g_sp[b * CC + c] * (1.0f / TT);
    }
    __syncthreads();
    if (tid < CR) {
        float a = b1[tid];
        for (int c = 0; c < CC; ++c) a += s_sh[c] * w1[c * CR + tid];
        h_sh[tid] = fmaxf(a, 0.f);
    }
    __syncthreads();
#pragma unroll
    for (int cb = 0; cb < 2; ++cb) {
        int c = tid + (cb << 8);
        float a = b2[c];
#pragma unroll
        for (int j = 0; j < CR; ++j) a += h_sh[j] * w2[j * CC + c];
        g_gate[b * CC + c] = 1.f / (1.f + expf(-a));
    }
}

// ============================================================================
// K4: fused y^T transpose + gate + residual + LN1. grid (T/32, B), 256 thr.
// ============================================================================
#define LN1T_SMEM (32 * 520 * 4)
__global__ __launch_bounds__(256) void ln1t_kernel(const float* __restrict__ x,
                                                   const float* __restrict__ w,
                                                   const float* __restrict__ bia)
{
    extern __shared__ float ys[];    // [32][520]
    const int t0 = (int)blockIdx.x << 5, b = blockIdx.y;
    const int tid = threadIdx.x, lane = tid & 31, wp = tid >> 5;

#pragma unroll
    for (int i = 0; i < 16; ++i) {
        int idx = i * 256 + tid;
        int c = idx >> 3, q = idx & 7;
        float4 v = *(const float4*)&g_yt[((size_t)c * BB + b) * TT + t0 + (q << 2)];
        ys[((q << 2) + 0) * 520 + c] = v.x;
        ys[((q << 2) + 1) * 520 + c] = v.y;
        ys[((q << 2) + 2) * 520 + c] = v.z;
        ys[((q << 2) + 3) * 520 + c] = v.w;
    }
    __syncthreads();

    const float4* gr = (const float4*)(g_gate + b * CC);
    const float4* w4p = (const float4*)w;
    const float4* b4p = (const float4*)bia;

#pragma unroll
    for (int rsub = 0; rsub < 4; ++rsub) {
        const int tt  = (wp << 2) + rsub;
        const int row = b * TT + t0 + tt;
        const float4* xr = (const float4*)(x + (size_t)row * CC);

        float4 v[4];
        float s = 0.f, sq = 0.f;
#pragma unroll
        for (int i = 0; i < 4; ++i) {
            int c4 = lane + (i << 5);
            float4 yv = *(float4*)&ys[tt * 520 + (c4 << 2)];
            float4 xv = xr[c4], gv = gr[c4], t;
            t.x = xv.x + yv.x * gv.x; t.y = xv.y + yv.y * gv.y;
            t.z = xv.z + yv.z * gv.z; t.w = xv.w + yv.w * gv.w;
            v[i] = t;
            s  += t.x + t.y + t.z + t.w;
            sq += t.x*t.x + t.y*t.y + t.z*t.z + t.w*t.w;
        }
#pragma unroll
        for (int o = 16; o; o >>= 1) {
            s  += __shfl_xor_sync(0xffffffffu, s,  o);
            sq += __shfl_xor_sync(0xffffffffu, sq, o);
        }
        float m    = s * (1.f / CC);
        float rstd = rsqrtf(sq * (1.f / CC) - m * m + 1e-5f);
        float4* out = (float4*)(g_y1 + (size_t)row * CC);
        __nv_bfloat162* oh = (__nv_bfloat162*)(g_y1h + (size_t)row * CC);
        __nv_bfloat162* ol = (__nv_bfloat162*)(g_y1l + (size_t)row * CC);
#pragma unroll
        for (int i = 0; i < 4; ++i) {
            int c4 = lane + (i << 5);
            float4 wv = w4p[c4], bv = b4p[c4], t = v[i], o4;
            o4.x = (t.x - m) * rstd * wv.x + bv.x;
            o4.y = (t.y - m) * rstd * wv.y + bv.y;
            o4.z = (t.z - m) * rstd * wv.z + bv.z;
            o4.w = (t.w - m) * rstd * wv.w + bv.w;
            out[c4] = o4;
            __nv_bfloat16 hx = __float2bfloat16(o4.x), hy = __float2bfloat16(o4.y);
            __nv_bfloat16 hz = __float2bfloat16(o4.z), hw = __float2bfloat16(o4.w);
            oh[c4*2+0] = __nv_bfloat162(hx, hy);
            oh[c4*2+1] = __nv_bfloat162(hz, hw);
            ol[c4*2+0] = __nv_bfloat162(__float2bfloat16(o4.x - __bfloat162float(hx)),
                                        __float2bfloat16(o4.y - __bfloat162float(hy)));
            ol[c4*2+1] = __nv_bfloat162(__float2bfloat16(o4.z - __bfloat162float(hz)),
                                        __float2bfloat16(o4.w - __bfloat162float(hw)));
        }
    }
}

// ============================================================================
// K5: fused up-GEMM + GLU on HMMA. CTA covers 64 a-cols + the SAME 64 g-cols.
// ============================================================================
__global__ __launch_bounds__(256) void up_gemm_glu_kernel(
    const __nv_bfloat16* __restrict__ Ahi, const __nv_bfloat16* __restrict__ Alo,
    const __nv_bfloat16* __restrict__ Bhi, const __nv_bfloat16* __restrict__ Blo,
    const float* __restrict__ ub)
{
    __shared__ __align__(128) uint8_t smem[2 * 20480];
    const uint32_t sbase = s2u(smem);

    const int tid  = threadIdx.x;
    const int lane = tid & 31;
    const int wid  = tid >> 5;
    const int wm   = wid & 3;
    const int wn   = wid >> 2;
    const int m0   = (int)blockIdx.y << 7;
    const int n0   = (int)blockIdx.x << 6;   // 64 a-cols per CTA

    const int lr = (lane & 7) + ((lane >> 3) & 1) * 8;
    const int lc = (lane >> 4) & 1;

    float acc[2][8][4];   // no 0..3 = a-cols, 4..7 = g-cols
#pragma unroll
    for (int a = 0; a < 2; ++a)
#pragma unroll
        for (int b = 0; b < 8; ++b)
#pragma unroll
            for (int c = 0; c < 4; ++c) acc[a][b][c] = 0.f;

    auto load_chunk = [&](int it, int buf) {
        const int s = it >> 4, kc = it & 15;
        const __nv_bfloat16* Ag = (s < 2) ? Ahi : Alo;
        const __nv_bfloat16* Bg = (s == 1) ? Blo : Bhi;
        const int k0 = kc << 5;
#pragma unroll
        for (int half = 0; half < 2; ++half) {
            int e   = tid + (half << 8);
            int row = e >> 2, c = e & 3;
            uint32_t sA = sbase + buf * 20480 + row * 80 + c * 16;
            cp16(sA, Ag + (size_t)(m0 + row) * CC + k0 + c * 8);
            int ng  = (row < 64) ? (n0 + row) : (448 + n0 + row);  // g rows at +512
            uint32_t sB = sbase + buf * 20480 + 10240 + row * 80 + c * 16;
            cp16(sB, Bg + (size_t)ng * CC + k0 + c * 8);
        }
        CP_COMMIT();
    };

    load_chunk(0, 0);

    for (int it = 0; it < 48; ++it) {
        const int buf = it & 1;
        if (it < 47) load_chunk(it + 1, buf ^ 1);
        if (it < 47) CP_WAIT1(); else CP_WAIT0();
        __syncthreads();

        const uint32_t abase = sbase + buf * 20480;
        const uint32_t bbase = abase + 10240;
#pragma unroll
        for (int kk = 0; kk < 2; ++kk) {
            uint32_t af[2][4], bf_[4][4];
#pragma unroll
            for (int mt = 0; mt < 2; ++mt)
                ldmx4(af[mt], abase + (uint32_t)((wm * 32 + mt * 16 + lr) * 80 + kk * 32 + lc * 16));
#pragma unroll
            for (int pr = 0; pr < 4; ++pr) {
                int rbase = (pr < 2) ? (wn * 32 + pr * 16) : (64 + wn * 32 + (pr - 2) * 16);
                ldmx4(bf_[pr], bbase + (uint32_t)((rbase + lr) * 80 + kk * 32 + lc * 16));
            }
#pragma unroll
            for (int mt = 0; mt < 2; ++mt)
#pragma unroll
                for (int no = 0; no < 8; ++no) {
                    uint32_t b0 = bf_[no >> 1][(no & 1)];
                    uint32_t b1 = bf_[no >> 1][(no & 1) + 2];
                    mma16816(acc[mt][no], af[mt], b0, b1);
                }
        }
        __syncthreads();
    }

    const int rr = lane >> 2, cc2 = (lane & 3) << 1;
#pragma unroll
    for (int mt = 0; mt < 2; ++mt) {
#pragma unroll
        for (int no = 0; no < 4; ++no) {
            int m = m0 + wm * 32 + mt * 16 + rr;
            int n = n0 + wn * 32 + no * 8 + cc2;
            float ba0 = ub[n], ba1 = ub[n + 1];
            float bg0 = ub[512 + n], bg1 = ub[512 + n + 1];
#pragma unroll
            for (int half = 0; half < 2; ++half) {
                int mm = m + half * 8;
                float a0 = acc[mt][no][half * 2 + 0] + ba0;
                float a1 = acc[mt][no][half * 2 + 1] + ba1;
                float g0 = acc[mt][no + 4][half * 2 + 0] + bg0;
                float g1 = acc[mt][no + 4][half * 2 + 1] + bg1;
                float h0 = 0.5f * a0 * (1.0f + erff(a0 * 0.70710678118654752f))
                         * (1.f / (1.f + expf(-g0)));
                float h1 = 0.5f * a1 * (1.0f + erff(a1 * 0.70710678118654752f))
                         * (1.f / (1.f + expf(-g1)));
                __nv_bfloat16 hh0 = __float2bfloat16(h0);
                __nv_bfloat16 hh1 = __float2bfloat16(h1);
                *(__nv_bfloat162*)&g_hh[(size_t)mm * HH + n] = __nv_bfloat162(hh0, hh1);
                *(__nv_bfloat162*)&g_hl[(size_t)mm * HH + n] = __nv_bfloat162(
                    __float2bfloat16(h0 - __bfloat162float(hh0)),
                    __float2bfloat16(h1 - __bfloat162float(hh1)));
            }
        }
    }
}

// ============================================================================
// K6: split-bf16 3-term GEMM on HMMA (down-projection).
// ============================================================================
__global__ __launch_bounds__(256) void down_gemm_kernel(
    const __nv_bfloat16* __restrict__ Ahi, const __nv_bfloat16* __restrict__ Alo,
    const __nv_bfloat16* __restrict__ Bhi, const __nv_bfloat16* __restrict__ Blo,
    float* __restrict__ out, const float* __restrict__ bias)
{
    __shared__ __align__(128) uint8_t smem[2 * 20480];
    const uint32_t sbase = s2u(smem);

    const int tid  = threadIdx.x;
    const int lane = tid & 31;
    const int wid  = tid >> 5;
    const int wm   = wid & 3;
    const int wn   = wid >> 2;
    const int m0   = (int)blockIdx.y << 7;
    const int n0   = (int)blockIdx.x << 7;

    const int lr = (lane & 7) + ((lane >> 3) & 1) * 8;
    const int lc = (lane >> 4) & 1;

    float acc[2][8][4];
#pragma unroll
    for (int a = 0; a < 2; ++a)
#pragma unroll
        for (int b = 0; b < 8; ++b)
#pragma unroll
            for (int c = 0; c < 4; ++c) acc[a][b][c] = 0.f;

    auto load_chunk = [&](int it, int buf) {
        const int s = it >> 4, kc = it & 15;
        const __nv_bfloat16* Ag = (s < 2) ? Ahi : Alo;
        const __nv_bfloat16* Bg = (s == 1) ? Blo : Bhi;
        const int k0 = kc << 5;
#pragma unroll
        for (int half = 0; half < 2; ++half) {
            int e   = tid + (half << 8);
            int row = e >> 2, c = e & 3;
            uint32_t sA = sbase + buf * 20480 + row * 80 + c * 16;
            cp16(sA, Ag + (size_t)(m0 + row) * CC + k0 + c * 8);
            uint32_t sB = sbase + buf * 20480 + 10240 + row * 80 + c * 16;
            cp16(sB, Bg + (size_t)(n0 + row) * CC + k0 + c * 8);
        }
        CP_COMMIT();
    };

    load_chunk(0, 0);

    for (int it = 0; it < 48; ++it) {
        const int buf = it & 1;
        if (it < 47) load_chunk(it + 1, buf ^ 1);
        if (it < 47) CP_WAIT1(); else CP_WAIT0();
        __syncthreads();

        const uint32_t abase = sbase + buf * 20480;
        const uint32_t bbase = abase + 10240;
#pragma unroll
        for (int kk = 0; kk < 2; ++kk) {
            uint32_t af[2][4], bf_[4][4];
#pragma unroll
            for (int mt = 0; mt < 2; ++mt)
                ldmx4(af[mt], abase + (uint32_t)((wm * 32 + mt * 16 + lr) * 80 + kk * 32 + lc * 16));
#pragma unroll
            for (int pr = 0; pr < 4; ++pr)
                ldmx4(bf_[pr], bbase + (uint32_t)((wn * 64 + pr * 16 + lr) * 80 + kk * 32 + lc * 16));
#pragma unroll
            for (int mt = 0; mt < 2; ++mt)
#pragma unroll
                for (int no = 0; no < 8; ++no) {
                    uint32_t b0 = bf_[no >> 1][(no & 1)];
                    uint32_t b1 = bf_[no >> 1][(no & 1) + 2];
                    mma16816(acc[mt][no], af[mt], b0, b1);
                }
        }
        __syncthreads();
    }

    const int rr = lane >> 2, cc2 = (lane & 3) << 1;
#pragma unroll
    for (int mt = 0; mt < 2; ++mt) {
#pragma unroll
        for (int no = 0; no < 8; ++no) {
            int m = m0 + wm * 32 + mt * 16 + rr;
            int n = n0 + wn * 64 + no * 8 + cc2;
            float b0 = bias[n], b1 = bias[n + 1];
            out[(size_t)m * CC + n]           = acc[mt][no][0] + b0;
            out[(size_t)m * CC + n + 1]       = acc[mt][no][1] + b1;
            out[(size_t)(m + 8) * CC + n]     = acc[mt][no][2] + b0;
            out[(size_t)(m + 8) * CC + n + 1] = acc[mt][no][3] + b1;
        }
    }
}

// ============================================================================
// K7: z2 = LN(y1+z, mix); out = LN(y1+z2, ln2). warp per row, fused.
// ============================================================================
__global__ __launch_bounds__(256) void ln_final_kernel(const float* __restrict__ mw,
                                                       const float* __restrict__ mb,
                                                       const float* __restrict__ w2,
                                                       const float* __restrict__ b2,
                                                       float* __restrict__ out)
{
    const int row  = blockIdx.x * 8 + (threadIdx.x >> 5);
    const int lane = threadIdx.x & 31;
    const float4* y1r = (const float4*)(g_y1 + (size_t)row * CC);
    const float4* zr  = (const float4*)(g_z  + (size_t)row * CC);

    float4 y1v[4], t[4];
    float s = 0.f, sq = 0.f;
#pragma unroll
    for (int i = 0; i < 4; ++i) {
        int c4 = lane + (i << 5);
        float4 yv = y1r[c4], zv = zr[c4], u;
        y1v[i] = yv;
        u.x = yv.x + zv.x; u.y = yv.y + zv.y; u.z = yv.z + zv.z; u.w = yv.w + zv.w;
        t[i] = u;
        s  += u.x + u.y + u.z + u.w;
        sq += u.x*u.x + u.y*u.y + u.z*u.z + u.w*u.w;
    }
#pragma unroll
    for (int o = 16; o; o >>= 1) {
        s  += __shfl_xor_sync(0xffffffffu, s,  o);
        sq += __shfl_xor_sync(0xffffffffu, sq, o);
    }
    float m    = s * (1.f / CC);
    float rstd = rsqrtf(sq * (1.f / CC) - m * m + 1e-5f);

    const float4* mw4 = (const float4*)mw;
    const float4* mb4 = (const float4*)mb;
    float s2 = 0.f, sq2 = 0.f;
#pragma unroll
    for (int i = 0; i < 4; ++i) {
        int c4 = lane + (i << 5);
        float4 wv = mw4[c4], bv = mb4[c4], u = t[i], yv = y1v[i], u2;
        u2.x = yv.x + ((u.x - m) * rstd * wv.x + bv.x);
        u2.y = yv.y + ((u.y - m) * rstd * wv.y + bv.y);
        u2.z = yv.z + ((u.z - m) * rstd * wv.z + bv.z);
        u2.w = yv.w + ((u.w - m) * rstd * wv.w + bv.w);
        t[i] = u2;
        s2  += u2.x + u2.y + u2.z + u2.w;
        sq2 += u2.x*u2.x + u2.y*u2.y + u2.z*u2.z + u2.w*u2.w;
    }
#pragma unroll
    for (int o = 16; o; o >>= 1) {
        s2  += __shfl_xor_sync(0xffffffffu, s2,  o);
        sq2 += __shfl_xor_sync(0xffffffffu, sq2, o);
    }
    float m2    = s2 * (1.f / CC);
    float rstd2 = rsqrtf(sq2 * (1.f / CC) - m2 * m2 + 1e-5f);

    float4* orow = (float4*)(out + (size_t)row * CC);
    const float4* w24 = (const float4*)w2;
    const float4* b24 = (const float4*)b2;
#pragma unroll
    for (int i = 0; i < 4; ++i) {
        int c4 = lane + (i << 5);
        float4 wv = w24[c4], bv = b24[c4], u = t[i], o4;
        o4.x = (u.x - m2) * rstd2 * wv.x + bv.x;
        o4.y = (u.y - m2) * rstd2 * wv.y + bv.y;
        o4.z = (u.z - m2) * rstd2 * wv.z + bv.z;
        o4.w = (u.w - m2) * rstd2 * wv.w + bv.w;
        orow[c4] = o4;
    }
}

// ============================================================================
extern "C" void kernel_launch(void* const* d_in, const int* in_sizes, int n_in,
                              void* d_out, int out_size)
{
    const float* x        = (const float*)d_in[0];
    const float* k        = (const float*)d_in[1];
    const float* se_w1    = (const float*)d_in[2];
    const float* se_b1    = (const float*)d_in[3];
    const float* se_w2    = (const float*)d_in[4];
    const float* se_b2    = (const float*)d_in[5];
    const float* ln1_w    = (const float*)d_in[6];
    const float* ln1_b    = (const float*)d_in[7];
    const float* up_w     = (const float*)d_in[8];
    const float* up_b     = (const float*)d_in[9];
    const float* down_w   = (const float*)d_in[10];
    const float* down_b   = (const float*)d_in[11];
    const float* mix_ln_w = (const float*)d_in[12];
    const float* mix_ln_b = (const float*)d_in[13];
    const float* ln2_w    = (const float*)d_in[14];
    const float* ln2_b    = (const float*)d_in[15];
    float* out = (float*)d_out;

    __nv_bfloat16 *ubh, *ubl, *dbh, *dbl, *y1h, *y1l, *hh, *hl;
    float *zz;
    cudaGetSymbolAddress((void**)&ubh, g_ubh);
    cudaGetSymbolAddress((void**)&ubl, g_ubl);
    cudaGetSymbolAddress((void**)&dbh, g_dbh);
    cudaGetSymbolAddress((void**)&dbl, g_dbl);
    cudaGetSymbolAddress((void**)&y1h, g_y1h);
    cudaGetSymbolAddress((void**)&y1l, g_y1l);
    cudaGetSymbolAddress((void**)&hh,  g_hh);
    cudaGetSymbolAddress((void**)&hl,  g_hl);
    cudaGetSymbolAddress((void**)&zz,  g_z);

    cudaFuncSetAttribute(conv_mma_kernel,
                         cudaFuncAttributeMaxDynamicSharedMemorySize, CONV_SMEM);
    cudaFuncSetAttribute(ln1t_kernel,
                         cudaFuncAttributeMaxDynamicSharedMemorySize, LN1T_SMEM);

    transpose_split_kernel<<<dim3(1024/32, 512/32), dim3(32, 8)>>>(up_w, CC, 1024, ubh, ubl);
    transpose_split_kernel<<<dim3( 512/32, 512/32), dim3(32, 8)>>>(down_w, HH, 512, dbh, dbl);
    prep_x_kernel   <<<dim3(CC/32, TT/32, BB), dim3(32, 8)>>>(x);
    conv_mma_kernel <<<CC, 512, CONV_SMEM>>>(k);
    se_kernel       <<<BB, 256>>>(se_w1, se_b1, se_w2, se_b2);
    ln1t_kernel     <<<dim3(TT/32, BB), 256, LN1T_SMEM>>>(x, ln1_w, ln1_b);
    up_gemm_glu_kernel<<<dim3(8, ROWS / 128), 256>>>(y1h, y1l, ubh, ubl, up_b);
    down_gemm_kernel  <<<dim3(4, ROWS / 128), 256>>>(hh, hl, dbh, dbl, zz, down_b);
    ln_final_kernel <<<ROWS / 8, 256>>>(mix_ln_w, mix_ln_b, ln2_w, ln2_b, out);
}

// round 14
// speedup vs baseline: 1.1275x; 1.0321x over previous
#include <cuda_runtime.h>
#include <cuda_bf16.h>
#include <math.h>
#include <stdint.h>

#define BB   8
#define TT   2048
#define CC   512
#define LL   2048
#define CR   32
#define HH   512
#define ROWS (BB*TT)   /* 16384 */

// ---------------- scratch (static device globals; no allocation) -------------
__device__ float g_yt[CC*BB*TT];            // conv output transposed [c][b][t]
__device__ float g_y1[BB*TT*CC];            // after SE gate + residual + LN1 (fp32)
__device__ __nv_bfloat16 g_y1h[ROWS*CC];    // y1 split hi
__device__ __nv_bfloat16 g_y1l[ROWS*CC];    // y1 split lo
__device__ __nv_bfloat16 g_hh [ROWS*HH];    // GLU hidden split hi
__device__ __nv_bfloat16 g_hl [ROWS*HH];    // GLU hidden split lo
__device__ float g_z [ROWS*CC];             // down-proj output
__device__ float g_sp[BB*CC];               // time-sums for SE pooling
__device__ float g_gate[BB*CC];             // SE gate
__device__ __nv_bfloat16 g_ubh[1024*CC];    // up_w^T  [N=1024][K=512] hi
__device__ __nv_bfloat16 g_ubl[1024*CC];    // up_w^T  lo
__device__ __nv_bfloat16 g_dbh[ CC*HH];     // down_w^T [N=512][K=512] hi
__device__ __nv_bfloat16 g_dbl[ CC*HH];     // down_w^T lo
__device__ __nv_bfloat16 g_xth[CC*BB*TT];   // x^T [c][b][t] hi
__device__ __nv_bfloat16 g_xtl[CC*BB*TT];   // x^T lo

// ===================== sm_100-base PTX helpers (NO tcgen05) ==================
__device__ __forceinline__ uint32_t s2u(const void* p) {
    uint32_t a;
    asm("{ .reg .u64 t; cvta.to.shared.u64 t, %1; cvt.u32.u64 %0, t; }"
        : "=r"(a) : "l"(p));
    return a;
}
__device__ __forceinline__ void cp16(uint32_t saddr, const void* gaddr) {
    asm volatile("cp.async.cg.shared.global [%0], [%1], 16;"
                 :: "r"(saddr), "l"(gaddr));
}
#define CP_COMMIT() asm volatile("cp.async.commit_group;" ::: "memory")
#define CP_WAIT1()  asm volatile("cp.async.wait_group 1;" ::: "memory")
#define CP_WAIT0()  asm volatile("cp.async.wait_group 0;" ::: "memory")

__device__ __forceinline__ void ldmx4(uint32_t* f, uint32_t addr) {
    asm volatile("ldmatrix.sync.aligned.m8n8.x4.shared.b16 {%0,%1,%2,%3}, [%4];"
                 : "=r"(f[0]), "=r"(f[1]), "=r"(f[2]), "=r"(f[3]) : "r"(addr));
}
__device__ __forceinline__ void lds64(uint32_t& h, uint32_t& l, uint32_t a) {
    asm volatile("ld.shared.v2.u32 {%0,%1}, [%2];" : "=r"(h), "=r"(l) : "r"(a));
}
__device__ __forceinline__ void mma16816(float* d, const uint32_t* a,
                                         uint32_t b0, uint32_t b1) {
    asm volatile("mma.sync.aligned.m16n8k16.row.col.f32.bf16.bf16.f32 "
                 "{%0,%1,%2,%3}, {%4,%5,%6,%7}, {%8,%9}, {%0,%1,%2,%3};"
                 : "+f"(d[0]), "+f"(d[1]), "+f"(d[2]), "+f"(d[3])
                 : "r"(a[0]), "r"(a[1]), "r"(a[2]), "r"(a[3]), "r"(b0), "r"(b1));
}

// ============================================================================
// K0a: tiled transpose + bf16 hi/lo split of GEMM weights: W[K][N] -> [N][K].
// ============================================================================
__global__ void transpose_split_kernel(const float* __restrict__ W, int K, int N,
                                       __nv_bfloat16* __restrict__ oh,
                                       __nv_bfloat16* __restrict__ ol)
{
    __shared__ float t[32][33];
    const int n0 = blockIdx.x << 5, k0 = blockIdx.y << 5;
    const int tx = threadIdx.x, ty = threadIdx.y;
#pragma unroll
    for (int r = 0; r < 4; ++r)
        t[ty + r * 8][tx] = W[(k0 + ty + r * 8) * N + n0 + tx];
    __syncthreads();
#pragma unroll
    for (int r = 0; r < 4; ++r) {
        int n = n0 + ty + r * 8, kk = k0 + tx;
        float w = t[tx][ty + r * 8];
        __nv_bfloat16 h = __float2bfloat16(w);
        oh[n * K + kk] = h;
        ol[n * K + kk] = __float2bfloat16(w - __bfloat162float(h));
    }
}

// ============================================================================
// K0b: x[b][t][c] fp32 -> x^T[c][b][t] bf16 hi/lo. grid (C/32, T/32, B).
// ============================================================================
__global__ void prep_x_kernel(const float* __restrict__ x)
{
    __shared__ float t[32][33];
    const int c0 = blockIdx.x << 5, t0 = blockIdx.y << 5, b = blockIdx.z;
    const int tx = threadIdx.x, ty = threadIdx.y;
#pragma unroll
    for (int r = 0; r < 4; ++r)
        t[ty + r * 8][tx] = x[((size_t)(b * TT) + t0 + ty + r * 8) * CC + c0 + tx];
    __syncthreads();
#pragma unroll
    for (int r = 0; r < 4; ++r) {
        int c = c0 + ty + r * 8, tt = t0 + tx;
        float v = t[tx][ty + r * 8];
        __nv_bfloat16 h = __float2bfloat16(v);
        size_t o = ((size_t)c * BB + b) * TT + tt;
        g_xth[o] = h;
        g_xtl[o] = __float2bfloat16(v - __bfloat162float(h));
    }
}

// ============================================================================
// K1: causal depthwise conv on HMMA. CTA = one channel, 16 warps (512 thr).
// R13 kernel with __launch_bounds__(512, 2): forces regs <= 64 so TWO CTAs
// co-reside per SM (R13's 66 regs dropped occupancy to 1 CTA/SM, 25%).
// A-fragments from PACKED (hi,lo) uint2 krev2 table: 3x LDS.64 per delta.
// SMEM: x hi (8x4112) | x lo (8x4112) | packed krev2 (2064 x uint2 = 16512B).
// ============================================================================
#define XR 4112
#define CONV_SMEM (65792 + 16512)
__global__ __launch_bounds__(512, 2) void conv_mma_kernel(const float* __restrict__ kg)
{
    extern __shared__ __align__(16) uint8_t smp[];
    const int tid = threadIdx.x, lane = tid & 31, w = tid >> 5;
    const int c = blockIdx.x;
    const uint32_t sbase = s2u(smp);
    const uint32_t xs_hi = sbase, xs_lo = sbase + 32896;
    const uint32_t kr2 = sbase + 65792;       // packed table
    float* sps = (float*)(smp + 65792);       // 8 floats, reused post-mainloop

    // stage x^T hi/lo: 2048 float4 over 512 threads = 4 iterations
    {
        const float4* srcH = (const float4*)(g_xth + (size_t)c * 16384);
        const float4* srcL = (const float4*)(g_xtl + (size_t)c * 16384);
#pragma unroll
        for (int r = 0; r < 4; ++r) {
            int idx = r * 512 + tid;
            int b = idx >> 8, q = idx & 255;
            float4 vh = srcH[b * 256 + q];
            float4 vl = srcL[b * 256 + q];
            *(float4*)(smp + b * XR + q * 16) = vh;
            *(float4*)(smp + 32896 + b * XR + q * 16) = vl;
        }
    }
    // build packed krev2 table: tp[idx] = {hi_pair, lo_pair}, idx = q + 16
    {
        const float* kc = kg + (size_t)c * LL;
        uint2* tp = (uint2*)(smp + 65792);
        for (int idx = tid; idx < 2064; idx += 512) {
            int p0 = idx - 16, p1 = idx - 17;
            float v0 = ((unsigned)p0 < 2048u) ? kc[2047 - p0] : 0.f;
            float v1 = ((unsigned)p1 < 2048u) ? kc[2047 - p1] : 0.f;
            __nv_bfloat16 h0 = __float2bfloat16(v0), h1 = __float2bfloat16(v1);
            __nv_bfloat16 l0 = __float2bfloat16(v0 - __bfloat162float(h0));
            __nv_bfloat16 l1 = __float2bfloat16(v1 - __bfloat162float(h1));
            uint32_t hp = (uint32_t)*(unsigned short*)&h0
                        | ((uint32_t)*(unsigned short*)&h1 << 16);
            uint32_t lp = (uint32_t)*(unsigned short*)&l0
                        | ((uint32_t)*(unsigned short*)&l1 << 16);
            tp[idx] = make_uint2(hp, lp);
        }
    }
    __syncthreads();

    const int g  = lane >> 2, t4 = lane & 3;
    const uint32_t aoff = (uint32_t)((g - 2 * t4 + 16) << 3);   // uint2 entries
    const uint32_t xb = ((lane < 16) ? xs_hi : xs_lo)
                      + (uint32_t)(lane & 7) * XR + ((lane >> 3) & 1) * 16;

    float acc[8][4];
#pragma unroll
    for (int s = 0; s < 8; ++s)
#pragma unroll
        for (int q = 0; q < 4; ++q) acc[s][q] = 0.f;

#pragma unroll
    for (int s = 0; s < 4; ++s) {
        const int ia = w + (s << 4);         // lower tile index  (0..63)
        const int ib = ia + 64;              // upper tile index  (64..127)
        uint32_t a_ad = kr2 + aoff;
        uint32_t bad_a = xb + (uint32_t)ia * 32;
        uint32_t bad_b = xb + (uint32_t)ib * 32;

        for (int d = 0; d <= ia; ++d) {      // both tiles live
            uint32_t ah[4], al[4], ba[4], bb[4];
            lds64(ah[0], al[0], a_ad);
            lds64(ah[1], al[1], a_ad + 64);
            lds64(ah[2], al[2], a_ad - 64);
            ah[3] = ah[0]; al[3] = al[0];
            ldmx4(ba, bad_a);                // ba[0..1]=hi, ba[2..3]=lo
            ldmx4(bb, bad_b);
            mma16816(acc[s],     ah, ba[0], ba[1]);
            mma16816(acc[s + 4], ah, bb[0], bb[1]);
            mma16816(acc[s],     ah, ba[2], ba[3]);
            mma16816(acc[s + 4], ah, bb[2], bb[3]);
            mma16816(acc[s],     al, ba[0], ba[1]);
            mma16816(acc[s + 4], al, bb[0], bb[1]);
            a_ad += 128; bad_a -= 32; bad_b -= 32;
        }
        for (int d = ia + 1; d <= ib; ++d) { // only upper tile live
            uint32_t ah[4], al[4], bb[4];
            lds64(ah[0], al[0], a_ad);
            lds64(ah[1], al[1], a_ad + 64);
            lds64(ah[2], al[2], a_ad - 64);
            ah[3] = ah[0]; al[3] = al[0];
            ldmx4(bb, bad_b);
            mma16816(acc[s + 4], ah, bb[0], bb[1]);
            mma16816(acc[s + 4], ah, bb[2], bb[3]);
            mma16816(acc[s + 4], al, bb[0], bb[1]);
            a_ad += 128; bad_b -= 32;
        }
    }
    __syncthreads();

    // epilogue: accs -> SMEM (reuse x region as fp32 [8][2056]); zero sps
    float* ys = (float*)smp;
    if (tid < 8) sps[tid] = 0.f;
    const int rr = lane >> 2, cb = (lane & 3) << 1;
#pragma unroll
    for (int s = 0; s < 8; ++s) {
        const int t0 = (w + ((s & 3) << 4) + ((s >> 2) << 6)) << 4;  // tiles w+16s', +64
        ys[cb * 2056 + t0 + rr]           = acc[s][0];
        ys[(cb + 1) * 2056 + t0 + rr]     = acc[s][1];
        ys[cb * 2056 + t0 + rr + 8]       = acc[s][2];
        ys[(cb + 1) * 2056 + t0 + rr + 8] = acc[s][3];
    }
    __syncthreads();

    // warp w: batch row w>>1, half w&1: coalesced y^T store + SE partial sum
    {
        const int b = w >> 1, hf = w & 1;
        float4* dst = (float4*)(g_yt + ((size_t)c * BB + b) * TT);
        float ssum = 0.f;
#pragma unroll
        for (int q = 0; q < 8; ++q) {
            int f4 = hf * 256 + q * 32 + lane;
            float4 v = *(float4*)&ys[b * 2056 + f4 * 4];
            dst[f4] = v;
            ssum += v.x + v.y + v.z + v.w;
        }
#pragma unroll
        for (int o = 16; o; o >>= 1) ssum += __shfl_xor_sync(0xffffffffu, ssum, o);
        if (lane == 0) atomicAdd(&sps[b], ssum);
    }
    __syncthreads();
    if (tid < 8) g_sp[tid * CC + c] = sps[tid];
}

// ============================================================================
// K3: SE bottleneck MLP + sigmoid.
// ============================================================================
__global__ __launch_bounds__(256) void se_kernel(const float* __restrict__ w1,
                                                 const float* __restrict__ b1,
                                                 const float* __restrict__ w2,
                                                 const float* __restrict__ b2)
{
    __shared__ float s_sh[CC];
    __shared__ float h_sh[CR];
    const int b = blockIdx.x, tid = threadIdx.x;
#pragma unroll
    for (int cb = 0; cb < 2; ++cb) {
        int c = tid + (cb << 8);
        s_sh[c] = g_sp[b * CC + c] * (1.0f / TT);
    }
    __syncthreads();
    if (tid < CR) {
        float a = b1[tid];
        for (int c = 0; c < CC; ++c) a += s_sh[c] * w1[c * CR + tid];
        h_sh[tid] = fmaxf(a, 0.f);
    }
    __syncthreads();
#pragma unroll
    for (int cb = 0; cb < 2; ++cb) {
        int c = tid + (cb << 8);
        float a = b2[c];
#pragma unroll
        for (int j = 0; j < CR; ++j) a += h_sh[j] * w2[j * CC + c];
        g_gate[b * CC + c] = 1.f / (1.f + expf(-a));
    }
}

// ============================================================================
// K4: fused y^T transpose + gate + residual + LN1. grid (T/32, B), 256 thr.
// ============================================================================
#define LN1T_SMEM (32 * 520 * 4)
__global__ __launch_bounds__(256) void ln1t_kernel(const float* __restrict__ x,
                                                   const float* __restrict__ w,
                                                   const float* __restrict__ bia)
{
    extern __shared__ float ys[];    // [32][520]
    const int t0 = (int)blockIdx.x << 5, b = blockIdx.y;
    const int tid = threadIdx.x, lane = tid & 31, wp = tid >> 5;

#pragma unroll
    for (int i = 0; i < 16; ++i) {
        int idx = i * 256 + tid;
        int c = idx >> 3, q = idx & 7;
        float4 v = *(const float4*)&g_yt[((size_t)c * BB + b) * TT + t0 + (q << 2)];
        ys[((q << 2) + 0) * 520 + c] = v.x;
        ys[((q << 2) + 1) * 520 + c] = v.y;
        ys[((q << 2) + 2) * 520 + c] = v.z;
        ys[((q << 2) + 3) * 520 + c] = v.w;
    }
    __syncthreads();

    const float4* gr = (const float4*)(g_gate + b * CC);
    const float4* w4p = (const float4*)w;
    const float4* b4p = (const float4*)bia;

#pragma unroll
    for (int rsub = 0; rsub < 4; ++rsub) {
        const int tt  = (wp << 2) + rsub;
        const int row = b * TT + t0 + tt;
        const float4* xr = (const float4*)(x + (size_t)row * CC);

        float4 v[4];
        float s = 0.f, sq = 0.f;
#pragma unroll
        for (int i = 0; i < 4; ++i) {
            int c4 = lane + (i << 5);
            float4 yv = *(float4*)&ys[tt * 520 + (c4 << 2)];
            float4 xv = xr[c4], gv = gr[c4], t;
            t.x = xv.x + yv.x * gv.x; t.y = xv.y + yv.y * gv.y;
            t.z = xv.z + yv.z * gv.z; t.w = xv.w + yv.w * gv.w;
            v[i] = t;
            s  += t.x + t.y + t.z + t.w;
            sq += t.x*t.x + t.y*t.y + t.z*t.z + t.w*t.w;
        }
#pragma unroll
        for (int o = 16; o; o >>= 1) {
            s  += __shfl_xor_sync(0xffffffffu, s,  o);
            sq += __shfl_xor_sync(0xffffffffu, sq, o);
        }
        float m    = s * (1.f / CC);
        float rstd = rsqrtf(sq * (1.f / CC) - m * m + 1e-5f);
        float4* out = (float4*)(g_y1 + (size_t)row * CC);
        __nv_bfloat162* oh = (__nv_bfloat162*)(g_y1h + (size_t)row * CC);
        __nv_bfloat162* ol = (__nv_bfloat162*)(g_y1l + (size_t)row * CC);
#pragma unroll
        for (int i = 0; i < 4; ++i) {
            int c4 = lane + (i << 5);
            float4 wv = w4p[c4], bv = b4p[c4], t = v[i], o4;
            o4.x = (t.x - m) * rstd * wv.x + bv.x;
            o4.y = (t.y - m) * rstd * wv.y + bv.y;
            o4.z = (t.z - m) * rstd * wv.z + bv.z;
            o4.w = (t.w - m) * rstd * wv.w + bv.w;
            out[c4] = o4;
            __nv_bfloat16 hx = __float2bfloat16(o4.x), hy = __float2bfloat16(o4.y);
            __nv_bfloat16 hz = __float2bfloat16(o4.z), hw = __float2bfloat16(o4.w);
            oh[c4*2+0] = __nv_bfloat162(hx, hy);
            oh[c4*2+1] = __nv_bfloat162(hz, hw);
            ol[c4*2+0] = __nv_bfloat162(__float2bfloat16(o4.x - __bfloat162float(hx)),
                                        __float2bfloat16(o4.y - __bfloat162float(hy)));
            ol[c4*2+1] = __nv_bfloat162(__float2bfloat16(o4.z - __bfloat162float(hz)),
                                        __float2bfloat16(o4.w - __bfloat162float(hw)));
        }
    }
}

// ============================================================================
// K5: fused up-GEMM + GLU on HMMA. CTA covers 64 a-cols + the SAME 64 g-cols.
// ============================================================================
__global__ __launch_bounds__(256) void up_gemm_glu_kernel(
    const __nv_bfloat16* __restrict__ Ahi, const __nv_bfloat16* __restrict__ Alo,
    const __nv_bfloat16* __restrict__ Bhi, const __nv_bfloat16* __restrict__ Blo,
    const float* __restrict__ ub)
{
    __shared__ __align__(128) uint8_t smem[2 * 20480];
    const uint32_t sbase = s2u(smem);

    const int tid  = threadIdx.x;
    const int lane = tid & 31;
    const int wid  = tid >> 5;
    const int wm   = wid & 3;
    const int wn   = wid >> 2;
    const int m0   = (int)blockIdx.y << 7;
    const int n0   = (int)blockIdx.x << 6;   // 64 a-cols per CTA

    const int lr = (lane & 7) + ((lane >> 3) & 1) * 8;
    const int lc = (lane >> 4) & 1;

    float acc[2][8][4];   // no 0..3 = a-cols, 4..7 = g-cols
#pragma unroll
    for (int a = 0; a < 2; ++a)
#pragma unroll
        for (int b = 0; b < 8; ++b)
#pragma unroll
            for (int c = 0; c < 4; ++c) acc[a][b][c] = 0.f;

    auto load_chunk = [&](int it, int buf) {
        const int s = it >> 4, kc = it & 15;
        const __nv_bfloat16* Ag = (s < 2) ? Ahi : Alo;
        const __nv_bfloat16* Bg = (s == 1) ? Blo : Bhi;
        const int k0 = kc << 5;
#pragma unroll
        for (int half = 0; half < 2; ++half) {
            int e   = tid + (half << 8);
            int row = e >> 2, c = e & 3;
            uint32_t sA = sbase + buf * 20480 + row * 80 + c * 16;
            cp16(sA, Ag + (size_t)(m0 + row) * CC + k0 + c * 8);
            int ng  = (row < 64) ? (n0 + row) : (448 + n0 + row);  // g rows at +512
            uint32_t sB = sbase + buf * 20480 + 10240 + row * 80 + c * 16;
            cp16(sB, Bg + (size_t)ng * CC + k0 + c * 8);
        }
        CP_COMMIT();
    };

    load_chunk(0, 0);

    for (int it = 0; it < 48; ++it) {
        const int buf = it & 1;
        if (it < 47) load_chunk(it + 1, buf ^ 1);
        if (it < 47) CP_WAIT1(); else CP_WAIT0();
        __syncthreads();

        const uint32_t abase = sbase + buf * 20480;
        const uint32_t bbase = abase + 10240;
#pragma unroll
        for (int kk = 0; kk < 2; ++kk) {
            uint32_t af[2][4], bf_[4][4];
#pragma unroll
            for (int mt = 0; mt < 2; ++mt)
                ldmx4(af[mt], abase + (uint32_t)((wm * 32 + mt * 16 + lr) * 80 + kk * 32 + lc * 16));
#pragma unroll
            for (int pr = 0; pr < 4; ++pr) {
                int rbase = (pr < 2) ? (wn * 32 + pr * 16) : (64 + wn * 32 + (pr - 2) * 16);
                ldmx4(bf_[pr], bbase + (uint32_t)((rbase + lr) * 80 + kk * 32 + lc * 16));
            }
#pragma unroll
            for (int mt = 0; mt < 2; ++mt)
#pragma unroll
                for (int no = 0; no < 8; ++no) {
                    uint32_t b0 = bf_[no >> 1][(no & 1)];
                    uint32_t b1 = bf_[no >> 1][(no & 1) + 2];
                    mma16816(acc[mt][no], af[mt], b0, b1);
                }
        }
        __syncthreads();
    }

    const int rr = lane >> 2, cc2 = (lane & 3) << 1;
#pragma unroll
    for (int mt = 0; mt < 2; ++mt) {
#pragma unroll
        for (int no = 0; no < 4; ++no) {
            int m = m0 + wm * 32 + mt * 16 + rr;
            int n = n0 + wn * 32 + no * 8 + cc2;
            float ba0 = ub[n], ba1 = ub[n + 1];
            float bg0 = ub[512 + n], bg1 = ub[512 + n + 1];
#pragma unroll
            for (int half = 0; half < 2; ++half) {
                int mm = m + half * 8;
                float a0 = acc[mt][no][half * 2 + 0] + ba0;
                float a1 = acc[mt][no][half * 2 + 1] + ba1;
                float g0 = acc[mt][no + 4][half * 2 + 0] + bg0;
                float g1 = acc[mt][no + 4][half * 2 + 1] + bg1;
                float h0 = 0.5f * a0 * (1.0f + erff(a0 * 0.70710678118654752f))
                         * (1.f / (1.f + expf(-g0)));
                float h1 = 0.5f * a1 * (1.0f + erff(a1 * 0.70710678118654752f))
                         * (1.f / (1.f + expf(-g1)));
                __nv_bfloat16 hh0 = __float2bfloat16(h0);
                __nv_bfloat16 hh1 = __float2bfloat16(h1);
                *(__nv_bfloat162*)&g_hh[(size_t)mm * HH + n] = __nv_bfloat162(hh0, hh1);
                *(__nv_bfloat162*)&g_hl[(size_t)mm * HH + n] = __nv_bfloat162(
                    __float2bfloat16(h0 - __bfloat162float(hh0)),
                    __float2bfloat16(h1 - __bfloat162float(hh1)));
            }
        }
    }
}

// ============================================================================
// K6: split-bf16 3-term GEMM on HMMA (down-projection).
// ============================================================================
__global__ __launch_bounds__(256) void down_gemm_kernel(
    const __nv_bfloat16* __restrict__ Ahi, const __nv_bfloat16* __restrict__ Alo,
    const __nv_bfloat16* __restrict__ Bhi, const __nv_bfloat16* __restrict__ Blo,
    float* __restrict__ out, const float* __restrict__ bias)
{
    __shared__ __align__(128) uint8_t smem[2 * 20480];
    const uint32_t sbase = s2u(smem);

    const int tid  = threadIdx.x;
    const int lane = tid & 31;
    const int wid  = tid >> 5;
    const int wm   = wid & 3;
    const int wn   = wid >> 2;
    const int m0   = (int)blockIdx.y << 7;
    const int n0   = (int)blockIdx.x << 7;

    const int lr = (lane & 7) + ((lane >> 3) & 1) * 8;
    const int lc = (lane >> 4) & 1;

    float acc[2][8][4];
#pragma unroll
    for (int a = 0; a < 2; ++a)
#pragma unroll
        for (int b = 0; b < 8; ++b)
#pragma unroll
            for (int c = 0; c < 4; ++c) acc[a][b][c] = 0.f;

    auto load_chunk = [&](int it, int buf) {
        const int s = it >> 4, kc = it & 15;
        const __nv_bfloat16* Ag = (s < 2) ? Ahi : Alo;
        const __nv_bfloat16* Bg = (s == 1) ? Blo : Bhi;
        const int k0 = kc << 5;
#pragma unroll
        for (int half = 0; half < 2; ++half) {
            int e   = tid + (half << 8);
            int row = e >> 2, c = e & 3;
            uint32_t sA = sbase + buf * 20480 + row * 80 + c * 16;
            cp16(sA, Ag + (size_t)(m0 + row) * CC + k0 + c * 8);
            uint32_t sB = sbase + buf * 20480 + 10240 + row * 80 + c * 16;
            cp16(sB, Bg + (size_t)(n0 + row) * CC + k0 + c * 8);
        }
        CP_COMMIT();
    };

    load_chunk(0, 0);

    for (int it = 0; it < 48; ++it) {
        const int buf = it & 1;
        if (it < 47) load_chunk(it + 1, buf ^ 1);
        if (it < 47) CP_WAIT1(); else CP_WAIT0();
        __syncthreads();

        const uint32_t abase = sbase + buf * 20480;
        const uint32_t bbase = abase + 10240;
#pragma unroll
        for (int kk = 0; kk < 2; ++kk) {
            uint32_t af[2][4], bf_[4][4];
#pragma unroll
            for (int mt = 0; mt < 2; ++mt)
                ldmx4(af[mt], abase + (uint32_t)((wm * 32 + mt * 16 + lr) * 80 + kk * 32 + lc * 16));
#pragma unroll
            for (int pr = 0; pr < 4; ++pr)
                ldmx4(bf_[pr], bbase + (uint32_t)((wn * 64 + pr * 16 + lr) * 80 + kk * 32 + lc * 16));
#pragma unroll
            for (int mt = 0; mt < 2; ++mt)
#pragma unroll
                for (int no = 0; no < 8; ++no) {
                    uint32_t b0 = bf_[no >> 1][(no & 1)];
                    uint32_t b1 = bf_[no >> 1][(no & 1) + 2];
                    mma16816(acc[mt][no], af[mt], b0, b1);
                }
        }
        __syncthreads();
    }

    const int rr = lane >> 2, cc2 = (lane & 3) << 1;
#pragma unroll
    for (int mt = 0; mt < 2; ++mt) {
#pragma unroll
        for (int no = 0; no < 8; ++no) {
            int m = m0 + wm * 32 + mt * 16 + rr;
            int n = n0 + wn * 64 + no * 8 + cc2;
            float b0 = bias[n], b1 = bias[n + 1];
            out[(size_t)m * CC + n]           = acc[mt][no][0] + b0;
            out[(size_t)m * CC + n + 1]       = acc[mt][no][1] + b1;
            out[(size_t)(m + 8) * CC + n]     = acc[mt][no][2] + b0;
            out[(size_t)(m + 8) * CC + n + 1] = acc[mt][no][3] + b1;
        }
    }
}

// ============================================================================
// K7: z2 = LN(y1+z, mix); out = LN(y1+z2, ln2). warp per row, fused.
// ============================================================================
__global__ __launch_bounds__(256) void ln_final_kernel(const float* __restrict__ mw,
                                                       const float* __restrict__ mb,
                                                       const float* __restrict__ w2,
                                                       const float* __restrict__ b2,
                                                       float* __restrict__ out)
{
    const int row  = blockIdx.x * 8 + (threadIdx.x >> 5);
    const int lane = threadIdx.x & 31;
    const float4* y1r = (const float4*)(g_y1 + (size_t)row * CC);
    const float4* zr  = (const float4*)(g_z  + (size_t)row * CC);

    float4 y1v[4], t[4];
    float s = 0.f, sq = 0.f;
#pragma unroll
    for (int i = 0; i < 4; ++i) {
        int c4 = lane + (i << 5);
        float4 yv = y1r[c4], zv = zr[c4], u;
        y1v[i] = yv;
        u.x = yv.x + zv.x; u.y = yv.y + zv.y; u.z = yv.z + zv.z; u.w = yv.w + zv.w;
        t[i] = u;
        s  += u.x + u.y + u.z + u.w;
        sq += u.x*u.x + u.y*u.y + u.z*u.z + u.w*u.w;
    }
#pragma unroll
    for (int o = 16; o; o >>= 1) {
        s  += __shfl_xor_sync(0xffffffffu, s,  o);
        sq += __shfl_xor_sync(0xffffffffu, sq, o);
    }
    float m    = s * (1.f / CC);
    float rstd = rsqrtf(sq * (1.f / CC) - m * m + 1e-5f);

    const float4* mw4 = (const float4*)mw;
    const float4* mb4 = (const float4*)mb;
    float s2 = 0.f, sq2 = 0.f;
#pragma unroll
    for (int i = 0; i < 4; ++i) {
        int c4 = lane + (i << 5);
        float4 wv = mw4[c4], bv = mb4[c4], u = t[i], yv = y1v[i], u2;
        u2.x = yv.x + ((u.x - m) * rstd * wv.x + bv.x);
        u2.y = yv.y + ((u.y - m) * rstd * wv.y + bv.y);
        u2.z = yv.z + ((u.z - m) * rstd * wv.z + bv.z);
        u2.w = yv.w + ((u.w - m) * rstd * wv.w + bv.w);
        t[i] = u2;
        s2  += u2.x + u2.y + u2.z + u2.w;
        sq2 += u2.x*u2.x + u2.y*u2.y + u2.z*u2.z + u2.w*u2.w;
    }
#pragma unroll
    for (int o = 16; o; o >>= 1) {
        s2  += __shfl_xor_sync(0xffffffffu, s2,  o);
        sq2 += __shfl_xor_sync(0xffffffffu, sq2, o);
    }
    float m2    = s2 * (1.f / CC);
    float rstd2 = rsqrtf(sq2 * (1.f / CC) - m2 * m2 + 1e-5f);

    float4* orow = (float4*)(out + (size_t)row * CC);
    const float4* w24 = (const float4*)w2;
    const float4* b24 = (const float4*)b2;
#pragma unroll
    for (int i = 0; i < 4; ++i) {
        int c4 = lane + (i << 5);
        float4 wv = w24[c4], bv = b24[c4], u = t[i], o4;
        o4.x = (u.x - m2) * rstd2 * wv.x + bv.x;
        o4.y = (u.y - m2) * rstd2 * wv.y + bv.y;
        o4.z = (u.z - m2) * rstd2 * wv.z + bv.z;
        o4.w = (u.w - m2) * rstd2 * wv.w + bv.w;
        orow[c4] = o4;
    }
}

// ============================================================================
extern "C" void kernel_launch(void* const* d_in, const int* in_sizes, int n_in,
                              void* d_out, int out_size)
{
    const float* x        = (const float*)d_in[0];
    const float* k        = (const float*)d_in[1];
    const float* se_w1    = (const float*)d_in[2];
    const float* se_b1    = (const float*)d_in[3];
    const float* se_w2    = (const float*)d_in[4];
    const float* se_b2    = (const float*)d_in[5];
    const float* ln1_w    = (const float*)d_in[6];
    const float* ln1_b    = (const float*)d_in[7];
    const float* up_w     = (const float*)d_in[8];
    const float* up_b     = (const float*)d_in[9];
    const float* down_w   = (const float*)d_in[10];
    const float* down_b   = (const float*)d_in[11];
    const float* mix_ln_w = (const float*)d_in[12];
    const float* mix_ln_b = (const float*)d_in[13];
    const float* ln2_w    = (const float*)d_in[14];
    const float* ln2_b    = (const float*)d_in[15];
    float* out = (float*)d_out;

    __nv_bfloat16 *ubh, *ubl, *dbh, *dbl, *y1h, *y1l, *hh, *hl;
    float *zz;
    cudaGetSymbolAddress((void**)&ubh, g_ubh);
    cudaGetSymbolAddress((void**)&ubl, g_ubl);
    cudaGetSymbolAddress((void**)&dbh, g_dbh);
    cudaGetSymbolAddress((void**)&dbl, g_dbl);
    cudaGetSymbolAddress((void**)&y1h, g_y1h);
    cudaGetSymbolAddress((void**)&y1l, g_y1l);
    cudaGetSymbolAddress((void**)&hh,  g_hh);
    cudaGetSymbolAddress((void**)&hl,  g_hl);
    cudaGetSymbolAddress((void**)&zz,  g_z);

    cudaFuncSetAttribute(conv_mma_kernel,
                         cudaFuncAttributeMaxDynamicSharedMemorySize, CONV_SMEM);
    cudaFuncSetAttribute(ln1t_kernel,
                         cudaFuncAttributeMaxDynamicSharedMemorySize, LN1T_SMEM);

    transpose_split_kernel<<<dim3(1024/32, 512/32), dim3(32, 8)>>>(up_w, CC, 1024, ubh, ubl);
    transpose_split_kernel<<<dim3( 512/32, 512/32), dim3(32, 8)>>>(down_w, HH, 512, dbh, dbl);
    prep_x_kernel   <<<dim3(CC/32, TT/32, BB), dim3(32, 8)>>>(x);
    conv_mma_kernel <<<CC, 512, CONV_SMEM>>>(k);
    se_kernel       <<<BB, 256>>>(se_w1, se_b1, se_w2, se_b2);
    ln1t_kernel     <<<dim3(TT/32, BB), 256, LN1T_SMEM>>>(x, ln1_w, ln1_b);
    up_gemm_glu_kernel<<<dim3(8, ROWS / 128), 256>>>(y1h, y1l, ubh, ubl, up_b);
    down_gemm_kernel  <<<dim3(4, ROWS / 128), 256>>>(hh, hl, dbh, dbl, zz, down_b);
    ln_final_kernel <<<ROWS / 8, 256>>>(mix_ln_w, mix_ln_b, ln2_w, ln2_b, out);
}

// round 16
// speedup vs baseline: 1.1356x; 1.0072x over previous
#include <cuda_runtime.h>
#include <cuda_bf16.h>
#include <math.h>
#include <stdint.h>

#define BB   8
#define TT   2048
#define CC   512
#define LL   2048
#define CR   32
#define HH   512
#define ROWS (BB*TT)   /* 16384 */

// ---------------- scratch (static device globals; no allocation) -------------
__device__ float g_yt[CC*BB*TT];            // conv output transposed [c][b][t]
__device__ float g_y1[BB*TT*CC];            // after SE gate + residual + LN1 (fp32)
__device__ __nv_bfloat16 g_y1h[ROWS*CC];    // y1 split hi
__device__ __nv_bfloat16 g_y1l[ROWS*CC];    // y1 split lo
__device__ __nv_bfloat16 g_hh [ROWS*HH];    // GLU hidden split hi
__device__ __nv_bfloat16 g_hl [ROWS*HH];    // GLU hidden split lo
__device__ float g_z [ROWS*CC];             // down-proj output
__device__ float g_sp[BB*CC];               // time-sums for SE pooling
__device__ float g_gate[BB*CC];             // SE gate
__device__ __nv_bfloat16 g_ubh[1024*CC];    // up_w^T  [N=1024][K=512] hi
__device__ __nv_bfloat16 g_ubl[1024*CC];    // up_w^T  lo
__device__ __nv_bfloat16 g_dbh[ CC*HH];     // down_w^T [N=512][K=512] hi
__device__ __nv_bfloat16 g_dbl[ CC*HH];     // down_w^T lo
__device__ __nv_bfloat16 g_xth[CC*BB*TT];   // x^T [c][b][t] hi
__device__ __nv_bfloat16 g_xtl[CC*BB*TT];   // x^T lo

// ===================== sm_100-base PTX helpers (NO tcgen05) ==================
__device__ __forceinline__ uint32_t s2u(const void* p) {
    uint32_t a;
    asm("{ .reg .u64 t; cvta.to.shared.u64 t, %1; cvt.u32.u64 %0, t; }"
        : "=r"(a) : "l"(p));
    return a;
}
__device__ __forceinline__ void cp16(uint32_t saddr, const void* gaddr) {
    asm volatile("cp.async.cg.shared.global [%0], [%1], 16;"
                 :: "r"(saddr), "l"(gaddr));
}
#define CP_COMMIT() asm volatile("cp.async.commit_group;" ::: "memory")
#define CP_WAIT1()  asm volatile("cp.async.wait_group 1;" ::: "memory")
#define CP_WAIT0()  asm volatile("cp.async.wait_group 0;" ::: "memory")

__device__ __forceinline__ void ldmx4(uint32_t* f, uint32_t addr) {
    asm volatile("ldmatrix.sync.aligned.m8n8.x4.shared.b16 {%0,%1,%2,%3}, [%4];"
                 : "=r"(f[0]), "=r"(f[1]), "=r"(f[2]), "=r"(f[3]) : "r"(addr));
}
__device__ __forceinline__ void lds32(uint32_t& v, uint32_t a) {
    asm volatile("ld.shared.b32 %0, [%1];" : "=r"(v) : "r"(a));
}
__device__ __forceinline__ void mma16816(float* d, const uint32_t* a,
                                         uint32_t b0, uint32_t b1) {
    asm volatile("mma.sync.aligned.m16n8k16.row.col.f32.bf16.bf16.f32 "
                 "{%0,%1,%2,%3}, {%4,%5,%6,%7}, {%8,%9}, {%0,%1,%2,%3};"
                 : "+f"(d[0]), "+f"(d[1]), "+f"(d[2]), "+f"(d[3])
                 : "r"(a[0]), "r"(a[1]), "r"(a[2]), "r"(a[3]), "r"(b0), "r"(b1));
}

// ============================================================================
// K0a: tiled transpose + bf16 hi/lo split of GEMM weights: W[K][N] -> [N][K].
// ============================================================================
__global__ void transpose_split_kernel(const float* __restrict__ W, int K, int N,
                                       __nv_bfloat16* __restrict__ oh,
                                       __nv_bfloat16* __restrict__ ol)
{
    __shared__ float t[32][33];
    const int n0 = blockIdx.x << 5, k0 = blockIdx.y << 5;
    const int tx = threadIdx.x, ty = threadIdx.y;
#pragma unroll
    for (int r = 0; r < 4; ++r)
        t[ty + r * 8][tx] = W[(k0 + ty + r * 8) * N + n0 + tx];
    __syncthreads();
#pragma unroll
    for (int r = 0; r < 4; ++r) {
        int n = n0 + ty + r * 8, kk = k0 + tx;
        float w = t[tx][ty + r * 8];
        __nv_bfloat16 h = __float2bfloat16(w);
        oh[n * K + kk] = h;
        ol[n * K + kk] = __float2bfloat16(w - __bfloat162float(h));
    }
}

// ============================================================================
// K0b: x[b][t][c] fp32 -> x^T[c][b][t] bf16 hi/lo. grid (C/32, T/32, B).
// ============================================================================
__global__ void prep_x_kernel(const float* __restrict__ x)
{
    __shared__ float t[32][33];
    const int c0 = blockIdx.x << 5, t0 = blockIdx.y << 5, b = blockIdx.z;
    const int tx = threadIdx.x, ty = threadIdx.y;
#pragma unroll
    for (int r = 0; r < 4; ++r)
        t[ty + r * 8][tx] = x[((size_t)(b * TT) + t0 + ty + r * 8) * CC + c0 + tx];
    __syncthreads();
#pragma unroll
    for (int r = 0; r < 4; ++r) {
        int c = c0 + ty + r * 8, tt = t0 + tx;
        float v = t[tx][ty + r * 8];
        __nv_bfloat16 h = __float2bfloat16(v);
        size_t o = ((size_t)c * BB + b) * TT + tt;
        g_xth[o] = h;
        g_xtl[o] = __float2bfloat16(v - __bfloat162float(h));
    }
}

// ============================================================================
// K1: causal depthwise conv on HMMA — EXACT R9 configuration (measured 164us:
// regs=64, 2 CTAs/SM, L1 76.6%, tensor 60.6%). 16 warps, pairing (s, s+4),
// A-fragments via 6x scalar LDS.32 from separate hi/lo krev2 tables.
// SMEM: x hi (8x4112) | x lo (8x4112) | krev2 hi 8320 | krev2 lo 8320.
// ============================================================================
#define XR 4112
#define CONV_SMEM (65792 + 2 * 8320)
__global__ __launch_bounds__(512) void conv_mma_kernel(const float* __restrict__ kg)
{
    extern __shared__ __align__(16) uint8_t smp[];
    const int tid = threadIdx.x, lane = tid & 31, w = tid >> 5;
    const int c = blockIdx.x;
    const uint32_t sbase = s2u(smp);
    const uint32_t xs_hi = sbase, xs_lo = sbase + 32896;
    const uint32_t kr2h = sbase + 65792, kr2l = kr2h + 8320;
    float* sps = (float*)(smp + 65792);   // 8 floats, reused post-mainloop

    // stage x^T hi/lo: 2048 float4 over 512 threads = 4 iterations
    {
        const float4* srcH = (const float4*)(g_xth + (size_t)c * 16384);
        const float4* srcL = (const float4*)(g_xtl + (size_t)c * 16384);
#pragma unroll
        for (int r = 0; r < 4; ++r) {
            int idx = r * 512 + tid;
            int b = idx >> 8, q = idx & 255;
            float4 vh = srcH[b * 256 + q];
            float4 vl = srcL[b * 256 + q];
            *(float4*)(smp + b * XR + q * 16) = vh;
            *(float4*)(smp + 32896 + b * XR + q * 16) = vl;
        }
    }
    // build krev2 pair tables (idx = q + 16, q in [-16, 2047])
    {
        const float* kc = kg + (size_t)c * LL;
        uint32_t* th = (uint32_t*)(smp + 65792);
        uint32_t* tl = (uint32_t*)(smp + 65792 + 8320);
        for (int idx = tid; idx < 2064; idx += 512) {
            int p0 = idx - 16, p1 = idx - 17;
            float v0 = ((unsigned)p0 < 2048u) ? kc[2047 - p0] : 0.f;
            float v1 = ((unsigned)p1 < 2048u) ? kc[2047 - p1] : 0.f;
            __nv_bfloat16 h0 = __float2bfloat16(v0), h1 = __float2bfloat16(v1);
            __nv_bfloat16 l0 = __float2bfloat16(v0 - __bfloat162float(h0));
            __nv_bfloat16 l1 = __float2bfloat16(v1 - __bfloat162float(h1));
            th[idx] = (uint32_t)*(unsigned short*)&h0
                    | ((uint32_t)*(unsigned short*)&h1 << 16);
            tl[idx] = (uint32_t)*(unsigned short*)&l0
                    | ((uint32_t)*(unsigned short*)&l1 << 16);
        }
    }
    __syncthreads();

    const int g  = lane >> 2, t4 = lane & 3;
    const uint32_t aoff = (uint32_t)((g - 2 * t4 + 16) << 2);   // byte off @ delta=0
    const uint32_t xb = ((lane < 16) ? xs_hi : xs_lo)
                      + (uint32_t)(lane & 7) * XR + ((lane >> 3) & 1) * 16;

    float acc[8][4];
#pragma unroll
    for (int s = 0; s < 8; ++s)
#pragma unroll
        for (int q = 0; q < 4; ++q) acc[s][q] = 0.f;

#pragma unroll
    for (int s = 0; s < 4; ++s) {
        const int ia = w + (s << 4);         // lower tile index  (0..63)
        const int ib = ia + 64;              // upper tile index  (64..127)
        uint32_t ah_ad = kr2h + aoff;
        uint32_t al_ad = kr2l + aoff;
        uint32_t bad_a = xb + (uint32_t)ia * 32;
        uint32_t bad_b = xb + (uint32_t)ib * 32;

        for (int d = 0; d <= ia; ++d) {      // both tiles live
            uint32_t ah[4], al[4], ba[4], bb[4];
            lds32(ah[0], ah_ad); lds32(ah[1], ah_ad + 32); lds32(ah[2], ah_ad - 32);
            ah[3] = ah[0];
            lds32(al[0], al_ad); lds32(al[1], al_ad + 32); lds32(al[2], al_ad - 32);
            al[3] = al[0];
            ldmx4(ba, bad_a);                // ba[0..1]=hi, ba[2..3]=lo
            ldmx4(bb, bad_b);
            mma16816(acc[s],     ah, ba[0], ba[1]);
            mma16816(acc[s + 4], ah, bb[0], bb[1]);
            mma16816(acc[s],     ah, ba[2], ba[3]);
            mma16816(acc[s + 4], ah, bb[2], bb[3]);
            mma16816(acc[s],     al, ba[0], ba[1]);
            mma16816(acc[s + 4], al, bb[0], bb[1]);
            ah_ad += 64; al_ad += 64; bad_a -= 32; bad_b -= 32;
        }
        for (int d = ia + 1; d <= ib; ++d) { // only upper tile live
            uint32_t ah[4], al[4], bb[4];
            lds32(ah[0], ah_ad); lds32(ah[1], ah_ad + 32); lds32(ah[2], ah_ad - 32);
            ah[3] = ah[0];
            lds32(al[0], al_ad); lds32(al[1], al_ad + 32); lds32(al[2], al_ad - 32);
            al[3] = al[0];
            ldmx4(bb, bad_b);
            mma16816(acc[s + 4], ah, bb[0], bb[1]);
            mma16816(acc[s + 4], ah, bb[2], bb[3]);
            mma16816(acc[s + 4], al, bb[0], bb[1]);
            ah_ad += 64; al_ad += 64; bad_b -= 32;
        }
    }
    __syncthreads();

    // epilogue: accs -> SMEM (reuse x region as fp32 [8][2056]); zero sps
    float* ys = (float*)smp;
    if (tid < 8) sps[tid] = 0.f;
    const int rr = lane >> 2, cb = (lane & 3) << 1;
#pragma unroll
    for (int s = 0; s < 8; ++s) {
        const int t0 = (w + ((s & 3) << 4) + ((s >> 2) << 6)) << 4;
        ys[cb * 2056 + t0 + rr]           = acc[s][0];
        ys[(cb + 1) * 2056 + t0 + rr]     = acc[s][1];
        ys[cb * 2056 + t0 + rr + 8]       = acc[s][2];
        ys[(cb + 1) * 2056 + t0 + rr + 8] = acc[s][3];
    }
    __syncthreads();

    // warp w: batch row w>>1, half w&1: coalesced y^T store + SE partial sum
    {
        const int b = w >> 1, hf = w & 1;
        float4* dst = (float4*)(g_yt + ((size_t)c * BB + b) * TT);
        float ssum = 0.f;
#pragma unroll
        for (int q = 0; q < 8; ++q) {
            int f4 = hf * 256 + q * 32 + lane;
            float4 v = *(float4*)&ys[b * 2056 + f4 * 4];
            dst[f4] = v;
            ssum += v.x + v.y + v.z + v.w;
        }
#pragma unroll
        for (int o = 16; o; o >>= 1) ssum += __shfl_xor_sync(0xffffffffu, ssum, o);
        if (lane == 0) atomicAdd(&sps[b], ssum);
    }
    __syncthreads();
    if (tid < 8) g_sp[tid * CC + c] = sps[tid];
}

// ============================================================================
// K3: SE bottleneck MLP + sigmoid.
// ============================================================================
__global__ __launch_bounds__(256) void se_kernel(const float* __restrict__ w1,
                                                 const float* __restrict__ b1,
                                                 const float* __restrict__ w2,
                                                 const float* __restrict__ b2)
{
    __shared__ float s_sh[CC];
    __shared__ float h_sh[CR];
    const int b = blockIdx.x, tid = threadIdx.x;
#pragma unroll
    for (int cb = 0; cb < 2; ++cb) {
        int c = tid + (cb << 8);
        s_sh[c] = g_sp[b * CC + c] * (1.0f / TT);
    }
    __syncthreads();
    if (tid < CR) {
        float a = b1[tid];
        for (int c = 0; c < CC; ++c) a += s_sh[c] * w1[c * CR + tid];
        h_sh[tid] = fmaxf(a, 0.f);
    }
    __syncthreads();
#pragma unroll
    for (int cb = 0; cb < 2; ++cb) {
        int c = tid + (cb << 8);
        float a = b2[c];
#pragma unroll
        for (int j = 0; j < CR; ++j) a += h_sh[j] * w2[j * CC + c];
        g_gate[b * CC + c] = 1.f / (1.f + expf(-a));
    }
}

// ============================================================================
// K4: fused y^T transpose + gate + residual + LN1. grid (T/32, B), 256 thr.
// ============================================================================
#define LN1T_SMEM (32 * 520 * 4)
__global__ __launch_bounds__(256) void ln1t_kernel(const float* __restrict__ x,
                                                   const float* __restrict__ w,
                                                   const float* __restrict__ bia)
{
    extern __shared__ float ys[];    // [32][520]
    const int t0 = (int)blockIdx.x << 5, b = blockIdx.y;
    const int tid = threadIdx.x, lane = tid & 31, wp = tid >> 5;

#pragma unroll
    for (int i = 0; i < 16; ++i) {
        int idx = i * 256 + tid;
        int c = idx >> 3, q = idx & 7;
        float4 v = *(const float4*)&g_yt[((size_t)c * BB + b) * TT + t0 + (q << 2)];
        ys[((q << 2) + 0) * 520 + c] = v.x;
        ys[((q << 2) + 1) * 520 + c] = v.y;
        ys[((q << 2) + 2) * 520 + c] = v.z;
        ys[((q << 2) + 3) * 520 + c] = v.w;
    }
    __syncthreads();

    const float4* gr = (const float4*)(g_gate + b * CC);
    const float4* w4p = (const float4*)w;
    const float4* b4p = (const float4*)bia;

#pragma unroll
    for (int rsub = 0; rsub < 4; ++rsub) {
        const int tt  = (wp << 2) + rsub;
        const int row = b * TT + t0 + tt;
        const float4* xr = (const float4*)(x + (size_t)row * CC);

        float4 v[4];
        float s = 0.f, sq = 0.f;
#pragma unroll
        for (int i = 0; i < 4; ++i) {
            int c4 = lane + (i << 5);
            float4 yv = *(float4*)&ys[tt * 520 + (c4 << 2)];
            float4 xv = xr[c4], gv = gr[c4], t;
            t.x = xv.x + yv.x * gv.x; t.y = xv.y + yv.y * gv.y;
            t.z = xv.z + yv.z * gv.z; t.w = xv.w + yv.w * gv.w;
            v[i] = t;
            s  += t.x + t.y + t.z + t.w;
            sq += t.x*t.x + t.y*t.y + t.z*t.z + t.w*t.w;
        }
#pragma unroll
        for (int o = 16; o; o >>= 1) {
            s  += __shfl_xor_sync(0xffffffffu, s,  o);
            sq += __shfl_xor_sync(0xffffffffu, sq, o);
        }
        float m    = s * (1.f / CC);
        float rstd = rsqrtf(sq * (1.f / CC) - m * m + 1e-5f);
        float4* out = (float4*)(g_y1 + (size_t)row * CC);
        __nv_bfloat162* oh = (__nv_bfloat162*)(g_y1h + (size_t)row * CC);
        __nv_bfloat162* ol = (__nv_bfloat162*)(g_y1l + (size_t)row * CC);
#pragma unroll
        for (int i = 0; i < 4; ++i) {
            int c4 = lane + (i << 5);
            float4 wv = w4p[c4], bv = b4p[c4], t = v[i], o4;
            o4.x = (t.x - m) * rstd * wv.x + bv.x;
            o4.y = (t.y - m) * rstd * wv.y + bv.y;
            o4.z = (t.z - m) * rstd * wv.z + bv.z;
            o4.w = (t.w - m) * rstd * wv.w + bv.w;
            out[c4] = o4;
            __nv_bfloat16 hx = __float2bfloat16(o4.x), hy = __float2bfloat16(o4.y);
            __nv_bfloat16 hz = __float2bfloat16(o4.z), hw = __float2bfloat16(o4.w);
            oh[c4*2+0] = __nv_bfloat162(hx, hy);
            oh[c4*2+1] = __nv_bfloat162(hz, hw);
            ol[c4*2+0] = __nv_bfloat162(__float2bfloat16(o4.x - __bfloat162float(hx)),
                                        __float2bfloat16(o4.y - __bfloat162float(hy)));
            ol[c4*2+1] = __nv_bfloat162(__float2bfloat16(o4.z - __bfloat162float(hz)),
                                        __float2bfloat16(o4.w - __bfloat162float(hw)));
        }
    }
}

// ============================================================================
// K5: fused up-GEMM + GLU on HMMA. 3-stage cp.async pipeline (prefetch dist 2,
// ONE __syncthreads per K-chunk). Dynamic smem: 3 x 20480 = 61440 B.
// ============================================================================
#define GEMM_SMEM (3 * 20480)
__global__ __launch_bounds__(256) void up_gemm_glu_kernel(
    const __nv_bfloat16* __restrict__ Ahi, const __nv_bfloat16* __restrict__ Alo,
    const __nv_bfloat16* __restrict__ Bhi, const __nv_bfloat16* __restrict__ Blo,
    const float* __restrict__ ub)
{
    extern __shared__ __align__(128) uint8_t gsm[];
    const uint32_t sbase = s2u(gsm);

    const int tid  = threadIdx.x;
    const int lane = tid & 31;
    const int wid  = tid >> 5;
    const int wm   = wid & 3;
    const int wn   = wid >> 2;
    const int m0   = (int)blockIdx.y << 7;
    const int n0   = (int)blockIdx.x << 6;   // 64 a-cols per CTA

    const int lr = (lane & 7) + ((lane >> 3) & 1) * 8;
    const int lc = (lane >> 4) & 1;

    float acc[2][8][4];   // no 0..3 = a-cols, 4..7 = g-cols
#pragma unroll
    for (int a = 0; a < 2; ++a)
#pragma unroll
        for (int b = 0; b < 8; ++b)
#pragma unroll
            for (int c = 0; c < 4; ++c) acc[a][b][c] = 0.f;

    auto load_chunk = [&](int it, int buf) {
        const int s = it >> 4, kc = it & 15;
        const __nv_bfloat16* Ag = (s < 2) ? Ahi : Alo;
        const __nv_bfloat16* Bg = (s == 1) ? Blo : Bhi;
        const int k0 = kc << 5;
#pragma unroll
        for (int half = 0; half < 2; ++half) {
            int e   = tid + (half << 8);
            int row = e >> 2, c = e & 3;
            uint32_t sA = sbase + buf * 20480 + row * 80 + c * 16;
            cp16(sA, Ag + (size_t)(m0 + row) * CC + k0 + c * 8);
            int ng  = (row < 64) ? (n0 + row) : (448 + n0 + row);  // g rows at +512
            uint32_t sB = sbase + buf * 20480 + 10240 + row * 80 + c * 16;
            cp16(sB, Bg + (size_t)ng * CC + k0 + c * 8);
        }
        CP_COMMIT();
    };

    load_chunk(0, 0);
    load_chunk(1, 1);

    for (int it = 0; it < 48; ++it) {
        const int buf = it % 3;
        if (it < 47) CP_WAIT1(); else CP_WAIT0();
        __syncthreads();
        if (it + 2 < 48) load_chunk(it + 2, (it + 2) % 3);

        const uint32_t abase = sbase + buf * 20480;
        const uint32_t bbase = abase + 10240;
#pragma unroll
        for (int kk = 0; kk < 2; ++kk) {
            uint32_t af[2][4], bf_[4][4];
#pragma unroll
            for (int mt = 0; mt < 2; ++mt)
                ldmx4(af[mt], abase + (uint32_t)((wm * 32 + mt * 16 + lr) * 80 + kk * 32 + lc * 16));
#pragma unroll
            for (int pr = 0; pr < 4; ++pr) {
                int rbase = (pr < 2) ? (wn * 32 + pr * 16) : (64 + wn * 32 + (pr - 2) * 16);
                ldmx4(bf_[pr], bbase + (uint32_t)((rbase + lr) * 80 + kk * 32 + lc * 16));
            }
#pragma unroll
            for (int mt = 0; mt < 2; ++mt)
#pragma unroll
                for (int no = 0; no < 8; ++no) {
                    uint32_t b0 = bf_[no >> 1][(no & 1)];
                    uint32_t b1 = bf_[no >> 1][(no & 1) + 2];
                    mma16816(acc[mt][no], af[mt], b0, b1);
                }
        }
    }

    const int rr = lane >> 2, cc2 = (lane & 3) << 1;
#pragma unroll
    for (int mt = 0; mt < 2; ++mt) {
#pragma unroll
        for (int no = 0; no < 4; ++no) {
            int m = m0 + wm * 32 + mt * 16 + rr;
            int n = n0 + wn * 32 + no * 8 + cc2;
            float ba0 = ub[n], ba1 = ub[n + 1];
            float bg0 = ub[512 + n], bg1 = ub[512 + n + 1];
#pragma unroll
            for (int half = 0; half < 2; ++half) {
                int mm = m + half * 8;
                float a0 = acc[mt][no][half * 2 + 0] + ba0;
                float a1 = acc[mt][no][half * 2 + 1] + ba1;
                float g0 = acc[mt][no + 4][half * 2 + 0] + bg0;
                float g1 = acc[mt][no + 4][half * 2 + 1] + bg1;
                float h0 = 0.5f * a0 * (1.0f + erff(a0 * 0.70710678118654752f))
                         * (1.f / (1.f + expf(-g0)));
                float h1 = 0.5f * a1 * (1.0f + erff(a1 * 0.70710678118654752f))
                         * (1.f / (1.f + expf(-g1)));
                __nv_bfloat16 hh0 = __float2bfloat16(h0);
                __nv_bfloat16 hh1 = __float2bfloat16(h1);
                *(__nv_bfloat162*)&g_hh[(size_t)mm * HH + n] = __nv_bfloat162(hh0, hh1);
                *(__nv_bfloat162*)&g_hl[(size_t)mm * HH + n] = __nv_bfloat162(
                    __float2bfloat16(h0 - __bfloat162float(hh0)),
                    __float2bfloat16(h1 - __bfloat162float(hh1)));
            }
        }
    }
}

// ============================================================================
// K6: split-bf16 3-term GEMM on HMMA (down-projection). 3-stage pipeline.
// ============================================================================
__global__ __launch_bounds__(256) void down_gemm_kernel(
    const __nv_bfloat16* __restrict__ Ahi, const __nv_bfloat16* __restrict__ Alo,
    const __nv_bfloat16* __restrict__ Bhi, const __nv_bfloat16* __restrict__ Blo,
    float* __restrict__ out, const float* __restrict__ bias)
{
    extern __shared__ __align__(128) uint8_t gsm[];
    const uint32_t sbase = s2u(gsm);

    const int tid  = threadIdx.x;
    const int lane = tid & 31;
    const int wid  = tid >> 5;
    const int wm   = wid & 3;
    const int wn   = wid >> 2;
    const int m0   = (int)blockIdx.y << 7;
    const int n0   = (int)blockIdx.x << 7;

    const int lr = (lane & 7) + ((lane >> 3) & 1) * 8;
    const int lc = (lane >> 4) & 1;

    float acc[2][8][4];
#pragma unroll
    for (int a = 0; a < 2; ++a)
#pragma unroll
        for (int b = 0; b < 8; ++b)
#pragma unroll
            for (int c = 0; c < 4; ++c) acc[a][b][c] = 0.f;

    auto load_chunk = [&](int it, int buf) {
        const int s = it >> 4, kc = it & 15;
        const __nv_bfloat16* Ag = (s < 2) ? Ahi : Alo;
        const __nv_bfloat16* Bg = (s == 1) ? Blo : Bhi;
        const int k0 = kc << 5;
#pragma unroll
        for (int half = 0; half < 2; ++half) {
            int e   = tid + (half << 8);
            int row = e >> 2, c = e & 3;
            uint32_t sA = sbase + buf * 20480 + row * 80 + c * 16;
            cp16(sA, Ag + (size_t)(m0 + row) * CC + k0 + c * 8);
            uint32_t sB = sbase + buf * 20480 + 10240 + row * 80 + c * 16;
            cp16(sB, Bg + (size_t)(n0 + row) * CC + k0 + c * 8);
        }
        CP_COMMIT();
    };

    load_chunk(0, 0);
    load_chunk(1, 1);

    for (int it = 0; it < 48; ++it) {
        const int buf = it % 3;
        if (it < 47) CP_WAIT1(); else CP_WAIT0();
        __syncthreads();
        if (it + 2 < 48) load_chunk(it + 2, (it + 2) % 3);

        const uint32_t abase = sbase + buf * 20480;
        const uint32_t bbase = abase + 10240;
#pragma unroll
        for (int kk = 0; kk < 2; ++kk) {
            uint32_t af[2][4], bf_[4][4];
#pragma unroll
            for (int mt = 0; mt < 2; ++mt)
                ldmx4(af[mt], abase + (uint32_t)((wm * 32 + mt * 16 + lr) * 80 + kk * 32 + lc * 16));
#pragma unroll
            for (int pr = 0; pr < 4; ++pr)
                ldmx4(bf_[pr], bbase + (uint32_t)((wn * 64 + pr * 16 + lr) * 80 + kk * 32 + lc * 16));
#pragma unroll
            for (int mt = 0; mt < 2; ++mt)
#pragma unroll
                for (int no = 0; no < 8; ++no) {
                    uint32_t b0 = bf_[no >> 1][(no & 1)];
                    uint32_t b1 = bf_[no >> 1][(no & 1) + 2];
                    mma16816(acc[mt][no], af[mt], b0, b1);
                }
        }
    }

    const int rr = lane >> 2, cc2 = (lane & 3) << 1;
#pragma unroll
    for (int mt = 0; mt < 2; ++mt) {
#pragma unroll
        for (int no = 0; no < 8; ++no) {
            int m = m0 + wm * 32 + mt * 16 + rr;
            int n = n0 + wn * 64 + no * 8 + cc2;
            float b0 = bias[n], b1 = bias[n + 1];
            out[(size_t)m * CC + n]           = acc[mt][no][0] + b0;
            out[(size_t)m * CC + n + 1]       = acc[mt][no][1] + b1;
            out[(size_t)(m + 8) * CC + n]     = acc[mt][no][2] + b0;
            out[(size_t)(m + 8) * CC + n + 1] = acc[mt][no][3] + b1;
        }
    }
}

// ============================================================================
// K7: z2 = LN(y1+z, mix); out = LN(y1+z2, ln2). warp per row, fused.
// ============================================================================
__global__ __launch_bounds__(256) void ln_final_kernel(const float* __restrict__ mw,
                                                       const float* __restrict__ mb,
                                                       const float* __restrict__ w2,
                                                       const float* __restrict__ b2,
                                                       float* __restrict__ out)
{
    const int row  = blockIdx.x * 8 + (threadIdx.x >> 5);
    const int lane = threadIdx.x & 31;
    const float4* y1r = (const float4*)(g_y1 + (size_t)row * CC);
    const float4* zr  = (const float4*)(g_z  + (size_t)row * CC);

    float4 y1v[4], t[4];
    float s = 0.f, sq = 0.f;
#pragma unroll
    for (int i = 0; i < 4; ++i) {
        int c4 = lane + (i << 5);
        float4 yv = y1r[c4], zv = zr[c4], u;
        y1v[i] = yv;
        u.x = yv.x + zv.x; u.y = yv.y + zv.y; u.z = yv.z + zv.z; u.w = yv.w + zv.w;
        t[i] = u;
        s  += u.x + u.y + u.z + u.w;
        sq += u.x*u.x + u.y*u.y + u.z*u.z + u.w*u.w;
    }
#pragma unroll
    for (int o = 16; o; o >>= 1) {
        s  += __shfl_xor_sync(0xffffffffu, s,  o);
        sq += __shfl_xor_sync(0xffffffffu, sq, o);
    }
    float m    = s * (1.f / CC);
    float rstd = rsqrtf(sq * (1.f / CC) - m * m + 1e-5f);

    const float4* mw4 = (const float4*)mw;
    const float4* mb4 = (const float4*)mb;
    float s2 = 0.f, sq2 = 0.f;
#pragma unroll
    for (int i = 0; i < 4; ++i) {
        int c4 = lane + (i << 5);
        float4 wv = mw4[c4], bv = mb4[c4], u = t[i], yv = y1v[i], u2;
        u2.x = yv.x + ((u.x - m) * rstd * wv.x + bv.x);
        u2.y = yv.y + ((u.y - m) * rstd * wv.y + bv.y);
        u2.z = yv.z + ((u.z - m) * rstd * wv.z + bv.z);
        u2.w = yv.w + ((u.w - m) * rstd * wv.w + bv.w);
        t[i] = u2;
        s2  += u2.x + u2.y + u2.z + u2.w;
        sq2 += u2.x*u2.x + u2.y*u2.y + u2.z*u2.z + u2.w*u2.w;
    }
#pragma unroll
    for (int o = 16; o; o >>= 1) {
        s2  += __shfl_xor_sync(0xffffffffu, s2,  o);
        sq2 += __shfl_xor_sync(0xffffffffu, sq2, o);
    }
    float m2    = s2 * (1.f / CC);
    float rstd2 = rsqrtf(sq2 * (1.f / CC) - m2 * m2 + 1e-5f);

    float4* orow = (float4*)(out + (size_t)row * CC);
    const float4* w24 = (const float4*)w2;
    const float4* b24 = (const float4*)b2;
#pragma unroll
    for (int i = 0; i < 4; ++i) {
        int c4 = lane + (i << 5);
        float4 wv = w24[c4], bv = b24[c4], u = t[i], o4;
        o4.x = (u.x - m2) * rstd2 * wv.x + bv.x;
        o4.y = (u.y - m2) * rstd2 * wv.y + bv.y;
        o4.z = (u.z - m2) * rstd2 * wv.z + bv.z;
        o4.w = (u.w - m2) * rstd2 * wv.w + bv.w;
        orow[c4] = o4;
    }
}

// ============================================================================
extern "C" void kernel_launch(void* const* d_in, const int* in_sizes, int n_in,
                              void* d_out, int out_size)
{
    const float* x        = (const float*)d_in[0];
    const float* k        = (const float*)d_in[1];
    const float* se_w1    = (const float*)d_in[2];
    const float* se_b1    = (const float*)d_in[3];
    const float* se_w2    = (const float*)d_in[4];
    const float* se_b2    = (const float*)d_in[5];
    const float* ln1_w    = (const float*)d_in[6];
    const float* ln1_b    = (const float*)d_in[7];
    const float* up_w     = (const float*)d_in[8];
    const float* up_b     = (const float*)d_in[9];
    const float* down_w   = (const float*)d_in[10];
    const float* down_b   = (const float*)d_in[11];
    const float* mix_ln_w = (const float*)d_in[12];
    const float* mix_ln_b = (const float*)d_in[13];
    const float* ln2_w    = (const float*)d_in[14];
    const float* ln2_b    = (const float*)d_in[15];
    float* out = (float*)d_out;

    __nv_bfloat16 *ubh, *ubl, *dbh, *dbl, *y1h, *y1l, *hh, *hl;
    float *zz;
    cudaGetSymbolAddress((void**)&ubh, g_ubh);
    cudaGetSymbolAddress((void**)&ubl, g_ubl);
    cudaGetSymbolAddress((void**)&dbh, g_dbh);
    cudaGetSymbolAddress((void**)&dbl, g_dbl);
    cudaGetSymbolAddress((void**)&y1h, g_y1h);
    cudaGetSymbolAddress((void**)&y1l, g_y1l);
    cudaGetSymbolAddress((void**)&hh,  g_hh);
    cudaGetSymbolAddress((void**)&hl,  g_hl);
    cudaGetSymbolAddress((void**)&zz,  g_z);

    cudaFuncSetAttribute(conv_mma_kernel,
                         cudaFuncAttributeMaxDynamicSharedMemorySize, CONV_SMEM);
    cudaFuncSetAttribute(ln1t_kernel,
                         cudaFuncAttributeMaxDynamicSharedMemorySize, LN1T_SMEM);
    cudaFuncSetAttribute(up_gemm_glu_kernel,
                         cudaFuncAttributeMaxDynamicSharedMemorySize, GEMM_SMEM);
    cudaFuncSetAttribute(down_gemm_kernel,
                         cudaFuncAttributeMaxDynamicSharedMemorySize, GEMM_SMEM);

    transpose_split_kernel<<<dim3(1024/32, 512/32), dim3(32, 8)>>>(up_w, CC, 1024, ubh, ubl);
    transpose_split_kernel<<<dim3( 512/32, 512/32), dim3(32, 8)>>>(down_w, HH, 512, dbh, dbl);
    prep_x_kernel   <<<dim3(CC/32, TT/32, BB), dim3(32, 8)>>>(x);
    conv_mma_kernel <<<CC, 512, CONV_SMEM>>>(k);
    se_kernel       <<<BB, 256>>>(se_w1, se_b1, se_w2, se_b2);
    ln1t_kernel     <<<dim3(TT/32, BB), 256, LN1T_SMEM>>>(x, ln1_w, ln1_b);
    up_gemm_glu_kernel<<<dim3(8, ROWS / 128), 256, GEMM_SMEM>>>(y1h, y1l, ubh, ubl, up_b);
    down_gemm_kernel  <<<dim3(4, ROWS / 128), 256, GEMM_SMEM>>>(hh, hl, dbh, dbl, zz, down_b);
    ln_final_kernel <<<ROWS / 8, 256>>>(mix_ln_w, mix_ln_b, ln2_w, ln2_b, out);
}